// round 2
// baseline (speedup 1.0000x reference)
#include <cuda_runtime.h>

#define NB 16
#define NC 128
#define NW 16384
#define TILE 64
#define NTILES 4096            // 16 batches * 256 tiles
#define SCALE_F 0.17677669529663687f   // 32^-0.5
#define LN_EPS 1e-5f

#define A_WP 260   // sWt pitch (floats): 260*4 %16==0, transpose-write stride %32==4 (conflict-free)
#define A_XP 68    // x/ek/v tile pitch
#define C_WP 136   // sWqt/sMt pitch
#define C_XP 68    // x/eq/y tile pitch

__device__ float g_S[NB * 4096];      // unnormalized context per (b,h,d,e)
__device__ float g_Z[NB * 128];       // k-softmax denominators per (b,h*32+d)
__device__ float g_M[NB * 128 * 128]; // per-batch output matrix [b][o][hd]

// ---------------------------------------------------------------------------
__global__ void k_zero() {
    int i = blockIdx.x * blockDim.x + threadIdx.x;  // 66*1024 = 67584 exactly
    if (i < NB * 4096) g_S[i] = 0.0f;
    else {
        int j = i - NB * 4096;
        if (j < NB * 128) g_Z[j] = 0.0f;
    }
}

// ---------------------------------------------------------------------------
// Kernel A: per (batch, 64-col tile): kv = W_kv @ x  (256x64, K=128), then
// accumulate S[h][d][e] += sum_n exp(k[d,n]) * v[e,n]  and  Z[d] += sum_n exp(k)
__global__ void __launch_bounds__(256, 1)
k_kvctx(const float* __restrict__ x, const float* __restrict__ Wqkv) {
    extern __shared__ float sm[];
    float* sWt = sm;                      // [128][A_WP]  W_kv transposed (k-major)
    float* sX  = sm + 128 * A_WP;         // [128][A_XP]  x tile, reused as ek
    float* sV  = sX + 128 * A_XP;         // [128][A_XP]  v tile

    const int tid = threadIdx.x;
    const int tr = tid >> 3;   // 0..31 -> 8 output rows each
    const int tc = tid & 7;    // 0..7  -> 8 output cols each

    // stage W_kv transposed: sWt[k][r] = Wqkv[(128+r)*128 + k]
    for (int idx = tid * 4; idx < 256 * 128; idx += 1024) {
        int r = idx >> 7, k = idx & 127;
        float4 w = *(const float4*)(Wqkv + (size_t)(128 + r) * 128 + k);
        sWt[(k + 0) * A_WP + r] = w.x;
        sWt[(k + 1) * A_WP + r] = w.y;
        sWt[(k + 2) * A_WP + r] = w.z;
        sWt[(k + 3) * A_WP + r] = w.w;
    }

    for (int tile = blockIdx.x; tile < NTILES; tile += gridDim.x) {
        int b = tile >> 8;
        int n0 = (tile & 255) * TILE;
        __syncthreads();   // W staged (1st iter) / prior S-phase reads done
        const float* xb = x + (size_t)b * NC * NW + n0;
        for (int idx = tid * 4; idx < 128 * 64; idx += 1024) {
            int r = idx >> 6, c = idx & 63;
            *(float4*)(sX + r * A_XP + c) = *(const float4*)(xb + (size_t)r * NW + c);
        }
        __syncthreads();

        float acc[8][8];
        #pragma unroll
        for (int i = 0; i < 8; i++)
            #pragma unroll
            for (int j = 0; j < 8; j++) acc[i][j] = 0.0f;

        #pragma unroll 4
        for (int k = 0; k < 128; k++) {
            float a[8], bb[8];
            *(float4*)(a)      = *(const float4*)(sWt + k * A_WP + tr * 8);
            *(float4*)(a + 4)  = *(const float4*)(sWt + k * A_WP + tr * 8 + 4);
            *(float4*)(bb)     = *(const float4*)(sX + k * A_XP + tc * 8);
            *(float4*)(bb + 4) = *(const float4*)(sX + k * A_XP + tc * 8 + 4);
            #pragma unroll
            for (int i = 0; i < 8; i++)
                #pragma unroll
                for (int j = 0; j < 8; j++)
                    acc[i][j] = fmaf(a[i], bb[j], acc[i][j]);
        }
        __syncthreads();   // all GEMM reads of sX done before ek overwrite

        if (tr < 16) {     // k channels -> ek = exp(k) into sX region
            #pragma unroll
            for (int i = 0; i < 8; i++) {
                int row = tr * 8 + i;
                float4 v0 = make_float4(__expf(acc[i][0]), __expf(acc[i][1]),
                                        __expf(acc[i][2]), __expf(acc[i][3]));
                float4 v1 = make_float4(__expf(acc[i][4]), __expf(acc[i][5]),
                                        __expf(acc[i][6]), __expf(acc[i][7]));
                *(float4*)(sX + row * A_XP + tc * 8)     = v0;
                *(float4*)(sX + row * A_XP + tc * 8 + 4) = v1;
            }
        } else {           // v channels
            #pragma unroll
            for (int i = 0; i < 8; i++) {
                int row = tr * 8 + i - 128;
                *(float4*)(sV + row * A_XP + tc * 8) =
                    make_float4(acc[i][0], acc[i][1], acc[i][2], acc[i][3]);
                *(float4*)(sV + row * A_XP + tc * 8 + 4) =
                    make_float4(acc[i][4], acc[i][5], acc[i][6], acc[i][7]);
            }
        }
        __syncthreads();

        // S accumulation: thread -> (h, d-block of 4, e-block of 4)
        {
            int h = tid >> 6, rem = tid & 63;
            int dblk = rem >> 3, eblk = rem & 7;
            const float* ekp = sX + (h * 32 + dblk * 4) * A_XP;
            const float* vp  = sV + (h * 32 + eblk * 4) * A_XP;
            float s[4][4];
            #pragma unroll
            for (int a2 = 0; a2 < 4; a2++)
                #pragma unroll
                for (int b2 = 0; b2 < 4; b2++) s[a2][b2] = 0.0f;
            #pragma unroll 4
            for (int n = 0; n < 64; n += 4) {
                float4 e[4], vv[4];
                #pragma unroll
                for (int a2 = 0; a2 < 4; a2++)
                    e[a2] = *(const float4*)(ekp + a2 * A_XP + n);
                #pragma unroll
                for (int b2 = 0; b2 < 4; b2++)
                    vv[b2] = *(const float4*)(vp + b2 * A_XP + n);
                #pragma unroll
                for (int a2 = 0; a2 < 4; a2++)
                    #pragma unroll
                    for (int b2 = 0; b2 < 4; b2++)
                        s[a2][b2] += e[a2].x * vv[b2].x + e[a2].y * vv[b2].y
                                   + e[a2].z * vv[b2].z + e[a2].w * vv[b2].w;
            }
            float* gS = g_S + b * 4096 + h * 1024 + dblk * 4 * 32 + eblk * 4;
            #pragma unroll
            for (int a2 = 0; a2 < 4; a2++)
                #pragma unroll
                for (int b2 = 0; b2 < 4; b2++)
                    atomicAdd(gS + a2 * 32 + b2, s[a2][b2]);
        }

        if (tid < 128) {
            float z = 0.0f;
            #pragma unroll 8
            for (int n = 0; n < 64; n++) z += sX[tid * A_XP + n];
            atomicAdd(g_Z + b * 128 + tid, z);
        }
    }
}

// ---------------------------------------------------------------------------
// Kernel B: M[b][o][h*32+d] = SCALE * sum_e Wout[o][h*32+e] * S[h][d][e]/(Z[h,d]*W)
__global__ void k_mbuild(const float* __restrict__ Wout) {
    __shared__ float sCtx[4096];
    __shared__ float sWo[16 * 128];
    int b = blockIdx.y, o0 = blockIdx.x * 16;
    int tid = threadIdx.x;

    for (int idx = tid * 4; idx < 4096; idx += 1024) {
        float4 sv = *(const float4*)(g_S + b * 4096 + idx);
        float z = g_Z[b * 128 + (idx >> 5)];
        float r = 1.0f / (z * (float)NW);
        sv.x *= r; sv.y *= r; sv.z *= r; sv.w *= r;
        *(float4*)(sCtx + idx) = sv;
    }
    for (int idx = tid * 4; idx < 2048; idx += 1024) {
        int r = idx >> 7, k = idx & 127;
        *(float4*)(sWo + idx) = *(const float4*)(Wout + (size_t)(o0 + r) * 128 + k);
    }
    __syncthreads();

    for (int idx = tid; idx < 2048; idx += 256) {
        int orr = idx >> 7, hd = idx & 127;
        int h = hd >> 5, d = hd & 31;
        const float* wrow = sWo + orr * 128 + h * 32;
        const float* crow = sCtx + h * 1024 + d * 32;
        float sum = 0.0f;
        #pragma unroll
        for (int e4 = 0; e4 < 8; e4++) {
            float4 w4 = *(const float4*)(wrow + e4 * 4);
            float4 c4 = *(const float4*)(crow + e4 * 4);
            sum += w4.x * c4.x + w4.y * c4.y + w4.z * c4.z + w4.w * c4.w;
        }
        g_M[b * 16384 + (o0 + orr) * 128 + hd] = SCALE_F * sum;
    }
}

// ---------------------------------------------------------------------------
// Kernel C: q = W_q @ x ; softmax over head-dim ; y = M_b @ qsm + b_out ; LayerNorm
__global__ void __launch_bounds__(256, 1)
k_qout(const float* __restrict__ x, const float* __restrict__ Wqkv,
       const float* __restrict__ b_out, const float* __restrict__ gamma,
       const float* __restrict__ beta, float* __restrict__ out) {
    extern __shared__ float sm[];
    float* sWqt = sm;                    // [128][C_WP] W_q transposed
    float* sMt  = sm + 128 * C_WP;       // [128][C_WP] M_b transposed (hd-major)
    float* sE   = sMt + 128 * C_WP;      // [128][C_XP] x tile / eq / y
    __shared__ float sBias[128], sGamma[128], sBeta[128], sStat[128];

    const int tid = threadIdx.x;
    const int tr = tid >> 4;   // 0..15 -> 8 rows
    const int tc = tid & 15;   // 0..15 -> 4 cols

    for (int idx = tid * 4; idx < 128 * 128; idx += 1024) {
        int r = idx >> 7, k = idx & 127;
        float4 w = *(const float4*)(Wqkv + (size_t)r * 128 + k);
        sWqt[(k + 0) * C_WP + r] = w.x;
        sWqt[(k + 1) * C_WP + r] = w.y;
        sWqt[(k + 2) * C_WP + r] = w.z;
        sWqt[(k + 3) * C_WP + r] = w.w;
    }
    if (tid < 128) {
        sBias[tid]  = b_out[tid];
        sGamma[tid] = gamma[tid];
        sBeta[tid]  = beta[tid];
    }

    int per = (NTILES + gridDim.x - 1) / gridDim.x;
    int lo = blockIdx.x * per;
    int hi = min(NTILES, lo + per);
    int curb = -1;

    for (int tile = lo; tile < hi; tile++) {
        int b = tile >> 8;
        int n0 = (tile & 255) * TILE;
        if (b != curb) {
            __syncthreads();   // prior GEMM2 reads of sMt complete
            for (int idx = tid * 4; idx < 128 * 128; idx += 1024) {
                int r = idx >> 7, k = idx & 127;
                float4 m = *(const float4*)(g_M + b * 16384 + idx);
                sMt[(k + 0) * C_WP + r] = m.x;
                sMt[(k + 1) * C_WP + r] = m.y;
                sMt[(k + 2) * C_WP + r] = m.z;
                sMt[(k + 3) * C_WP + r] = m.w;
            }
            curb = b;
        }
        __syncthreads();   // covers sWqt/sMt writes + prior out-write reads of sE
        const float* xb = x + (size_t)b * NC * NW + n0;
        for (int idx = tid * 4; idx < 8192; idx += 1024) {
            int r = idx >> 6, c = idx & 63;
            *(float4*)(sE + r * C_XP + c) = *(const float4*)(xb + (size_t)r * NW + c);
        }
        __syncthreads();

        // GEMM1: q tile
        float acc[8][4];
        #pragma unroll
        for (int i = 0; i < 8; i++)
            #pragma unroll
            for (int j = 0; j < 4; j++) acc[i][j] = 0.0f;
        #pragma unroll 4
        for (int k = 0; k < 128; k++) {
            float a[8];
            *(float4*)(a)     = *(const float4*)(sWqt + k * C_WP + tr * 8);
            *(float4*)(a + 4) = *(const float4*)(sWqt + k * C_WP + tr * 8 + 4);
            float4 bb = *(const float4*)(sE + k * C_XP + tc * 4);
            #pragma unroll
            for (int i = 0; i < 8; i++) {
                acc[i][0] = fmaf(a[i], bb.x, acc[i][0]);
                acc[i][1] = fmaf(a[i], bb.y, acc[i][1]);
                acc[i][2] = fmaf(a[i], bb.z, acc[i][2]);
                acc[i][3] = fmaf(a[i], bb.w, acc[i][3]);
            }
        }
        __syncthreads();   // x reads done; reuse sE as eq
        #pragma unroll
        for (int i = 0; i < 8; i++) {
            float4 v = make_float4(__expf(acc[i][0]), __expf(acc[i][1]),
                                   __expf(acc[i][2]), __expf(acc[i][3]));
            *(float4*)(sE + (tr * 8 + i) * C_XP + tc * 4) = v;
        }
        __syncthreads();
        // head-softmax denominators + in-place rescale: thread <-> (h, col)
        {
            int h = tid >> 6, c = tid & 63;
            float den = 0.0f;
            #pragma unroll 8
            for (int d = 0; d < 32; d++) den += sE[(h * 32 + d) * C_XP + c];
            float rd = 1.0f / den;
            #pragma unroll 8
            for (int d = 0; d < 32; d++) sE[(h * 32 + d) * C_XP + c] *= rd;
        }
        __syncthreads();

        // GEMM2: y = M_b @ qsm
        float acc2[8][4];
        #pragma unroll
        for (int i = 0; i < 8; i++)
            #pragma unroll
            for (int j = 0; j < 4; j++) acc2[i][j] = 0.0f;
        #pragma unroll 4
        for (int k = 0; k < 128; k++) {
            float a[8];
            *(float4*)(a)     = *(const float4*)(sMt + k * C_WP + tr * 8);
            *(float4*)(a + 4) = *(const float4*)(sMt + k * C_WP + tr * 8 + 4);
            float4 bb = *(const float4*)(sE + k * C_XP + tc * 4);
            #pragma unroll
            for (int i = 0; i < 8; i++) {
                acc2[i][0] = fmaf(a[i], bb.x, acc2[i][0]);
                acc2[i][1] = fmaf(a[i], bb.y, acc2[i][1]);
                acc2[i][2] = fmaf(a[i], bb.z, acc2[i][2]);
                acc2[i][3] = fmaf(a[i], bb.w, acc2[i][3]);
            }
        }
        __syncthreads();   // qsm reads done; reuse sE as y
        #pragma unroll
        for (int i = 0; i < 8; i++) {
            float bi = sBias[tr * 8 + i];
            float4 v = make_float4(acc2[i][0] + bi, acc2[i][1] + bi,
                                   acc2[i][2] + bi, acc2[i][3] + bi);
            *(float4*)(sE + (tr * 8 + i) * C_XP + tc * 4) = v;
        }
        __syncthreads();
        // LayerNorm stats per column (biased variance)
        if (tid < 64) {
            float s = 0.0f, sq = 0.0f;
            #pragma unroll 8
            for (int r = 0; r < 128; r++) {
                float v = sE[r * C_XP + tid];
                s += v; sq += v * v;
            }
            float mean = s * (1.0f / 128.0f);
            float var = sq * (1.0f / 128.0f) - mean * mean;
            sStat[tid * 2]     = mean;
            sStat[tid * 2 + 1] = rsqrtf(var + LN_EPS);
        }
        __syncthreads();
        float* ob = out + (size_t)b * NC * NW + n0;
        for (int idx = tid * 4; idx < 8192; idx += 1024) {
            int r = idx >> 6, c = idx & 63;
            float4 v = *(const float4*)(sE + r * C_XP + c);
            float g = sGamma[r], be = sBeta[r];
            v.x = (v.x - sStat[2 * c])           * sStat[2 * c + 1]       * g + be;
            v.y = (v.y - sStat[2 * (c + 1)])     * sStat[2 * (c + 1) + 1] * g + be;
            v.z = (v.z - sStat[2 * (c + 2)])     * sStat[2 * (c + 2) + 1] * g + be;
            v.w = (v.w - sStat[2 * (c + 3)])     * sStat[2 * (c + 3) + 1] * g + be;
            *(float4*)(ob + (size_t)r * NW + c) = v;
        }
    }
}

// ---------------------------------------------------------------------------
extern "C" void kernel_launch(void* const* d_in, const int* in_sizes, int n_in,
                              void* d_out, int out_size) {
    const float* x    = (const float*)d_in[0];
    const float* Wqkv = (const float*)d_in[1];
    const float* Wout = (const float*)d_in[2];
    const float* bo   = (const float*)d_in[3];
    const float* gm   = (const float*)d_in[4];
    const float* bt   = (const float*)d_in[5];
    float* out = (float*)d_out;

    const int SMEM_A = (128 * A_WP + 2 * 128 * A_XP) * 4;  // 202752
    const int SMEM_C = (2 * 128 * C_WP + 128 * C_XP) * 4;  // 174080
    cudaFuncSetAttribute(k_kvctx, cudaFuncAttributeMaxDynamicSharedMemorySize, SMEM_A);
    cudaFuncSetAttribute(k_qout,  cudaFuncAttributeMaxDynamicSharedMemorySize, SMEM_C);

    k_zero<<<66, 1024>>>();
    k_kvctx<<<152, 256, SMEM_A>>>(x, Wqkv);
    k_mbuild<<<dim3(8, 16), 256>>>(Wout);
    k_qout<<<152, 256, SMEM_C>>>(x, Wqkv, bo, gm, bt, out);
}

// round 3
// speedup vs baseline: 1.0012x; 1.0012x over previous
#include <cuda_runtime.h>

#define NB 16
#define NC 128
#define NW 16384
#define TILE 64
#define NTILES 4096            // 16 batches * 256 tiles
#define SCALE_F 0.17677669529663687f   // 32^-0.5
#define LN_EPS 1e-5f

#define A_WP 260   // sWt pitch (floats): 260*4 %16==0, transpose-write stride %32==4 (conflict-free)
#define A_XP 68    // x/ek/v tile pitch
#define C_WP 136   // sWqt/sMt pitch
#define C_XP 68    // x/eq/y tile pitch

__device__ float g_S[NB * 4096];      // unnormalized context per (b,h,d,e)
__device__ float g_Z[NB * 128];       // k-softmax denominators per (b,h*32+d)
__device__ float g_M[NB * 128 * 128]; // per-batch output matrix [b][o][hd]

// ---------------------------------------------------------------------------
__global__ void k_zero() {
    int i = blockIdx.x * blockDim.x + threadIdx.x;  // 66*1024 = 67584 exactly
    if (i < NB * 4096) g_S[i] = 0.0f;
    else {
        int j = i - NB * 4096;
        if (j < NB * 128) g_Z[j] = 0.0f;
    }
}

// ---------------------------------------------------------------------------
// Kernel A: per (batch, 64-col tile): kv = W_kv @ x  (256x64, K=128), then
// accumulate S[h][d][e] += sum_n exp(k[d,n]) * v[e,n]  and  Z[d] += sum_n exp(k)
__global__ void __launch_bounds__(256, 1)
k_kvctx(const float* __restrict__ x, const float* __restrict__ Wqkv) {
    extern __shared__ float sm[];
    float* sWt = sm;                      // [128][A_WP]  W_kv transposed (k-major)
    float* sX  = sm + 128 * A_WP;         // [128][A_XP]  x tile, reused as ek
    float* sV  = sX + 128 * A_XP;         // [128][A_XP]  v tile

    const int tid = threadIdx.x;
    const int tr = tid >> 3;   // 0..31 -> 8 output rows each
    const int tc = tid & 7;    // 0..7  -> 8 output cols each

    // stage W_kv transposed: sWt[k][r] = Wqkv[(128+r)*128 + k]
    for (int idx = tid * 4; idx < 256 * 128; idx += 1024) {
        int r = idx >> 7, k = idx & 127;
        float4 w = *(const float4*)(Wqkv + (size_t)(128 + r) * 128 + k);
        sWt[(k + 0) * A_WP + r] = w.x;
        sWt[(k + 1) * A_WP + r] = w.y;
        sWt[(k + 2) * A_WP + r] = w.z;
        sWt[(k + 3) * A_WP + r] = w.w;
    }

    for (int tile = blockIdx.x; tile < NTILES; tile += gridDim.x) {
        int b = tile >> 8;
        int n0 = (tile & 255) * TILE;
        __syncthreads();   // W staged (1st iter) / prior S-phase reads done
        const float* xb = x + (size_t)b * NC * NW + n0;
        for (int idx = tid * 4; idx < 128 * 64; idx += 1024) {
            int r = idx >> 6, c = idx & 63;
            *(float4*)(sX + r * A_XP + c) = *(const float4*)(xb + (size_t)r * NW + c);
        }
        __syncthreads();

        float acc[8][8];
        #pragma unroll
        for (int i = 0; i < 8; i++)
            #pragma unroll
            for (int j = 0; j < 8; j++) acc[i][j] = 0.0f;

        #pragma unroll 4
        for (int k = 0; k < 128; k++) {
            float a[8], bb[8];
            *(float4*)(a)      = *(const float4*)(sWt + k * A_WP + tr * 8);
            *(float4*)(a + 4)  = *(const float4*)(sWt + k * A_WP + tr * 8 + 4);
            *(float4*)(bb)     = *(const float4*)(sX + k * A_XP + tc * 8);
            *(float4*)(bb + 4) = *(const float4*)(sX + k * A_XP + tc * 8 + 4);
            #pragma unroll
            for (int i = 0; i < 8; i++)
                #pragma unroll
                for (int j = 0; j < 8; j++)
                    acc[i][j] = fmaf(a[i], bb[j], acc[i][j]);
        }
        __syncthreads();   // all GEMM reads of sX done before ek overwrite

        if (tr < 16) {     // k channels -> ek = exp(k) into sX region
            #pragma unroll
            for (int i = 0; i < 8; i++) {
                int row = tr * 8 + i;
                float4 v0 = make_float4(__expf(acc[i][0]), __expf(acc[i][1]),
                                        __expf(acc[i][2]), __expf(acc[i][3]));
                float4 v1 = make_float4(__expf(acc[i][4]), __expf(acc[i][5]),
                                        __expf(acc[i][6]), __expf(acc[i][7]));
                *(float4*)(sX + row * A_XP + tc * 8)     = v0;
                *(float4*)(sX + row * A_XP + tc * 8 + 4) = v1;
            }
        } else {           // v channels
            #pragma unroll
            for (int i = 0; i < 8; i++) {
                int row = tr * 8 + i - 128;
                *(float4*)(sV + row * A_XP + tc * 8) =
                    make_float4(acc[i][0], acc[i][1], acc[i][2], acc[i][3]);
                *(float4*)(sV + row * A_XP + tc * 8 + 4) =
                    make_float4(acc[i][4], acc[i][5], acc[i][6], acc[i][7]);
            }
        }
        __syncthreads();

        // S accumulation: thread -> (h, d-block of 4, e-block of 4)
        {
            int h = tid >> 6, rem = tid & 63;
            int dblk = rem >> 3, eblk = rem & 7;
            const float* ekp = sX + (h * 32 + dblk * 4) * A_XP;
            const float* vp  = sV + (h * 32 + eblk * 4) * A_XP;
            float s[4][4];
            #pragma unroll
            for (int a2 = 0; a2 < 4; a2++)
                #pragma unroll
                for (int b2 = 0; b2 < 4; b2++) s[a2][b2] = 0.0f;
            #pragma unroll 4
            for (int n = 0; n < 64; n += 4) {
                float4 e[4], vv[4];
                #pragma unroll
                for (int a2 = 0; a2 < 4; a2++)
                    e[a2] = *(const float4*)(ekp + a2 * A_XP + n);
                #pragma unroll
                for (int b2 = 0; b2 < 4; b2++)
                    vv[b2] = *(const float4*)(vp + b2 * A_XP + n);
                #pragma unroll
                for (int a2 = 0; a2 < 4; a2++)
                    #pragma unroll
                    for (int b2 = 0; b2 < 4; b2++)
                        s[a2][b2] += e[a2].x * vv[b2].x + e[a2].y * vv[b2].y
                                   + e[a2].z * vv[b2].z + e[a2].w * vv[b2].w;
            }
            float* gS = g_S + b * 4096 + h * 1024 + dblk * 4 * 32 + eblk * 4;
            #pragma unroll
            for (int a2 = 0; a2 < 4; a2++)
                #pragma unroll
                for (int b2 = 0; b2 < 4; b2++)
                    atomicAdd(gS + a2 * 32 + b2, s[a2][b2]);
        }

        if (tid < 128) {
            float z = 0.0f;
            #pragma unroll 8
            for (int n = 0; n < 64; n++) z += sX[tid * A_XP + n];
            atomicAdd(g_Z + b * 128 + tid, z);
        }
    }
}

// ---------------------------------------------------------------------------
// Kernel B: M[b][o][h*32+d] = SCALE * sum_e Wout[o][h*32+e] * S[h][d][e]/(Z[h,d]*W)
__global__ void k_mbuild(const float* __restrict__ Wout) {
    __shared__ float sCtx[4096];
    __shared__ float sWo[16 * 128];
    int b = blockIdx.y, o0 = blockIdx.x * 16;
    int tid = threadIdx.x;

    for (int idx = tid * 4; idx < 4096; idx += 1024) {
        float4 sv = *(const float4*)(g_S + b * 4096 + idx);
        float z = g_Z[b * 128 + (idx >> 5)];
        float r = 1.0f / (z * (float)NW);
        sv.x *= r; sv.y *= r; sv.z *= r; sv.w *= r;
        *(float4*)(sCtx + idx) = sv;
    }
    for (int idx = tid * 4; idx < 2048; idx += 1024) {
        int r = idx >> 7, k = idx & 127;
        *(float4*)(sWo + idx) = *(const float4*)(Wout + (size_t)(o0 + r) * 128 + k);
    }
    __syncthreads();

    for (int idx = tid; idx < 2048; idx += 256) {
        int orr = idx >> 7, hd = idx & 127;
        int h = hd >> 5, d = hd & 31;
        const float* wrow = sWo + orr * 128 + h * 32;
        const float* crow = sCtx + h * 1024 + d * 32;
        float sum = 0.0f;
        #pragma unroll
        for (int e4 = 0; e4 < 8; e4++) {
            float4 w4 = *(const float4*)(wrow + e4 * 4);
            float4 c4 = *(const float4*)(crow + e4 * 4);
            sum += w4.x * c4.x + w4.y * c4.y + w4.z * c4.z + w4.w * c4.w;
        }
        g_M[b * 16384 + (o0 + orr) * 128 + hd] = SCALE_F * sum;
    }
}

// ---------------------------------------------------------------------------
// Kernel C: q = W_q @ x ; softmax over head-dim ; y = M_b @ qsm + b_out ; LayerNorm
__global__ void __launch_bounds__(256, 1)
k_qout(const float* __restrict__ x, const float* __restrict__ Wqkv,
       const float* __restrict__ b_out, const float* __restrict__ gamma,
       const float* __restrict__ beta, float* __restrict__ out) {
    extern __shared__ float sm[];
    float* sWqt = sm;                    // [128][C_WP] W_q transposed
    float* sMt  = sm + 128 * C_WP;       // [128][C_WP] M_b transposed (hd-major)
    float* sE   = sMt + 128 * C_WP;      // [128][C_XP] x tile / eq / y
    __shared__ float sBias[128], sGamma[128], sBeta[128], sStat[128];

    const int tid = threadIdx.x;
    const int tr = tid >> 4;   // 0..15 -> 8 rows
    const int tc = tid & 15;   // 0..15 -> 4 cols

    for (int idx = tid * 4; idx < 128 * 128; idx += 1024) {
        int r = idx >> 7, k = idx & 127;
        float4 w = *(const float4*)(Wqkv + (size_t)r * 128 + k);
        sWqt[(k + 0) * C_WP + r] = w.x;
        sWqt[(k + 1) * C_WP + r] = w.y;
        sWqt[(k + 2) * C_WP + r] = w.z;
        sWqt[(k + 3) * C_WP + r] = w.w;
    }
    if (tid < 128) {
        sBias[tid]  = b_out[tid];
        sGamma[tid] = gamma[tid];
        sBeta[tid]  = beta[tid];
    }

    int per = (NTILES + gridDim.x - 1) / gridDim.x;
    int lo = blockIdx.x * per;
    int hi = min(NTILES, lo + per);
    int curb = -1;

    for (int tile = lo; tile < hi; tile++) {
        int b = tile >> 8;
        int n0 = (tile & 255) * TILE;
        if (b != curb) {
            __syncthreads();   // prior GEMM2 reads of sMt complete
            for (int idx = tid * 4; idx < 128 * 128; idx += 1024) {
                int r = idx >> 7, k = idx & 127;
                float4 m = *(const float4*)(g_M + b * 16384 + idx);
                sMt[(k + 0) * C_WP + r] = m.x;
                sMt[(k + 1) * C_WP + r] = m.y;
                sMt[(k + 2) * C_WP + r] = m.z;
                sMt[(k + 3) * C_WP + r] = m.w;
            }
            curb = b;
        }
        __syncthreads();   // covers sWqt/sMt writes + prior out-write reads of sE
        const float* xb = x + (size_t)b * NC * NW + n0;
        for (int idx = tid * 4; idx < 8192; idx += 1024) {
            int r = idx >> 6, c = idx & 63;
            *(float4*)(sE + r * C_XP + c) = *(const float4*)(xb + (size_t)r * NW + c);
        }
        __syncthreads();

        // GEMM1: q tile
        float acc[8][4];
        #pragma unroll
        for (int i = 0; i < 8; i++)
            #pragma unroll
            for (int j = 0; j < 4; j++) acc[i][j] = 0.0f;
        #pragma unroll 4
        for (int k = 0; k < 128; k++) {
            float a[8];
            *(float4*)(a)     = *(const float4*)(sWqt + k * C_WP + tr * 8);
            *(float4*)(a + 4) = *(const float4*)(sWqt + k * C_WP + tr * 8 + 4);
            float4 bb = *(const float4*)(sE + k * C_XP + tc * 4);
            #pragma unroll
            for (int i = 0; i < 8; i++) {
                acc[i][0] = fmaf(a[i], bb.x, acc[i][0]);
                acc[i][1] = fmaf(a[i], bb.y, acc[i][1]);
                acc[i][2] = fmaf(a[i], bb.z, acc[i][2]);
                acc[i][3] = fmaf(a[i], bb.w, acc[i][3]);
            }
        }
        __syncthreads();   // x reads done; reuse sE as eq
        #pragma unroll
        for (int i = 0; i < 8; i++) {
            float4 v = make_float4(__expf(acc[i][0]), __expf(acc[i][1]),
                                   __expf(acc[i][2]), __expf(acc[i][3]));
            *(float4*)(sE + (tr * 8 + i) * C_XP + tc * 4) = v;
        }
        __syncthreads();
        // head-softmax denominators + in-place rescale: thread <-> (h, col)
        {
            int h = tid >> 6, c = tid & 63;
            float den = 0.0f;
            #pragma unroll 8
            for (int d = 0; d < 32; d++) den += sE[(h * 32 + d) * C_XP + c];
            float rd = 1.0f / den;
            #pragma unroll 8
            for (int d = 0; d < 32; d++) sE[(h * 32 + d) * C_XP + c] *= rd;
        }
        __syncthreads();

        // GEMM2: y = M_b @ qsm
        float acc2[8][4];
        #pragma unroll
        for (int i = 0; i < 8; i++)
            #pragma unroll
            for (int j = 0; j < 4; j++) acc2[i][j] = 0.0f;
        #pragma unroll 4
        for (int k = 0; k < 128; k++) {
            float a[8];
            *(float4*)(a)     = *(const float4*)(sMt + k * C_WP + tr * 8);
            *(float4*)(a + 4) = *(const float4*)(sMt + k * C_WP + tr * 8 + 4);
            float4 bb = *(const float4*)(sE + k * C_XP + tc * 4);
            #pragma unroll
            for (int i = 0; i < 8; i++) {
                acc2[i][0] = fmaf(a[i], bb.x, acc2[i][0]);
                acc2[i][1] = fmaf(a[i], bb.y, acc2[i][1]);
                acc2[i][2] = fmaf(a[i], bb.z, acc2[i][2]);
                acc2[i][3] = fmaf(a[i], bb.w, acc2[i][3]);
            }
        }
        __syncthreads();   // qsm reads done; reuse sE as y
        #pragma unroll
        for (int i = 0; i < 8; i++) {
            float bi = sBias[tr * 8 + i];
            float4 v = make_float4(acc2[i][0] + bi, acc2[i][1] + bi,
                                   acc2[i][2] + bi, acc2[i][3] + bi);
            *(float4*)(sE + (tr * 8 + i) * C_XP + tc * 4) = v;
        }
        __syncthreads();
        // LayerNorm stats per column (biased variance)
        if (tid < 64) {
            float s = 0.0f, sq = 0.0f;
            #pragma unroll 8
            for (int r = 0; r < 128; r++) {
                float v = sE[r * C_XP + tid];
                s += v; sq += v * v;
            }
            float mean = s * (1.0f / 128.0f);
            float var = sq * (1.0f / 128.0f) - mean * mean;
            sStat[tid * 2]     = mean;
            sStat[tid * 2 + 1] = rsqrtf(var + LN_EPS);
        }
        __syncthreads();
        float* ob = out + (size_t)b * NC * NW + n0;
        for (int idx = tid * 4; idx < 8192; idx += 1024) {
            int r = idx >> 6, c = idx & 63;
            float4 v = *(const float4*)(sE + r * C_XP + c);
            float g = sGamma[r], be = sBeta[r];
            v.x = (v.x - sStat[2 * c])           * sStat[2 * c + 1]       * g + be;
            v.y = (v.y - sStat[2 * (c + 1)])     * sStat[2 * (c + 1) + 1] * g + be;
            v.z = (v.z - sStat[2 * (c + 2)])     * sStat[2 * (c + 2) + 1] * g + be;
            v.w = (v.w - sStat[2 * (c + 3)])     * sStat[2 * (c + 3) + 1] * g + be;
            *(float4*)(ob + (size_t)r * NW + c) = v;
        }
    }
}

// ---------------------------------------------------------------------------
extern "C" void kernel_launch(void* const* d_in, const int* in_sizes, int n_in,
                              void* d_out, int out_size) {
    const float* x    = (const float*)d_in[0];
    const float* Wqkv = (const float*)d_in[1];
    const float* Wout = (const float*)d_in[2];
    const float* bo   = (const float*)d_in[3];
    const float* gm   = (const float*)d_in[4];
    const float* bt   = (const float*)d_in[5];
    float* out = (float*)d_out;

    const int SMEM_A = (128 * A_WP + 2 * 128 * A_XP) * 4;  // 202752
    const int SMEM_C = (2 * 128 * C_WP + 128 * C_XP) * 4;  // 174080
    cudaFuncSetAttribute(k_kvctx, cudaFuncAttributeMaxDynamicSharedMemorySize, SMEM_A);
    cudaFuncSetAttribute(k_qout,  cudaFuncAttributeMaxDynamicSharedMemorySize, SMEM_C);

    k_zero<<<66, 1024>>>();
    k_kvctx<<<152, 256, SMEM_A>>>(x, Wqkv);
    k_mbuild<<<dim3(8, 16), 256>>>(Wout);
    k_qout<<<152, 256, SMEM_C>>>(x, Wqkv, bo, gm, bt, out);
}

// round 5
// speedup vs baseline: 1.7983x; 1.7961x over previous
#include <cuda_runtime.h>
#include <cstdint>

#define NB 16
#define NCH 128
#define NW 16384
#define NTILES 4096
#define GRID_SM 152
#define SCALE_F 0.17677669529663687f
#define LN_EPS 1e-5f

__device__ float g_S[NB * 4096];
__device__ float g_Z[NB * 128];
__device__ float g_M[NB * 128 * 128];

__device__ __forceinline__ uint32_t smem_u32(const void* p) {
    uint32_t a;
    asm("{ .reg .u64 t; cvta.to.shared.u64 t, %1; cvt.u32.u64 %0, t; }" : "=r"(a) : "l"(p));
    return a;
}
__device__ __forceinline__ void bf16_split2(float a, float b, uint32_t& h, uint32_t& l) {
    asm("cvt.rn.bf16x2.f32 %0, %1, %2;" : "=r"(h) : "f"(b), "f"(a));
    float ra = a - __uint_as_float(h << 16);
    float rb = b - __uint_as_float(h & 0xFFFF0000u);
    asm("cvt.rn.bf16x2.f32 %0, %1, %2;" : "=r"(l) : "f"(rb), "f"(ra));
}
__device__ __forceinline__ void ldsm_x4(uint32_t* a, uint32_t addr) {
    asm volatile("ldmatrix.sync.aligned.m8n8.x4.shared.b16 {%0,%1,%2,%3}, [%4];"
                 : "=r"(a[0]), "=r"(a[1]), "=r"(a[2]), "=r"(a[3]) : "r"(addr));
}
__device__ __forceinline__ void ldsm_x4t(uint32_t* a, uint32_t addr) {
    asm volatile("ldmatrix.sync.aligned.m8n8.x4.trans.shared.b16 {%0,%1,%2,%3}, [%4];"
                 : "=r"(a[0]), "=r"(a[1]), "=r"(a[2]), "=r"(a[3]) : "r"(addr));
}
__device__ __forceinline__ void mma16816(float* c, const uint32_t* a, const uint32_t* b) {
    asm volatile("mma.sync.aligned.m16n8k16.row.col.f32.bf16.bf16.f32 "
                 "{%0,%1,%2,%3},{%4,%5,%6,%7},{%8,%9},{%0,%1,%2,%3};"
                 : "+f"(c[0]), "+f"(c[1]), "+f"(c[2]), "+f"(c[3])
                 : "r"(a[0]), "r"(a[1]), "r"(a[2]), "r"(a[3]), "r"(b[0]), "r"(b[1]));
}

// fp32 row of 128 -> two bf16 planes in smem, rows of 256B, XOR-16B swizzle
__device__ __forceinline__ void w_row_sts(char* sm, uint32_t oh, uint32_t ol,
                                          const float* __restrict__ src,
                                          int nrows, int tid) {
    for (int i = 0; i < nrows * 32; i += 256) {
        int idx = (tid + i) * 4;
        int m = idx >> 7, k = idx & 127;
        float4 w = *(const float4*)(src + m * 128 + k);
        uint32_t h0, l0, h1, l1;
        bf16_split2(w.x, w.y, h0, l0);
        bf16_split2(w.z, w.w, h1, l1);
        uint32_t byte = (uint32_t)(m * 256) + (((uint32_t)(k * 2)) ^ (((uint32_t)m & 7) << 4));
        *(uint2*)(sm + oh + byte) = make_uint2(h0, h1);
        *(uint2*)(sm + ol + byte) = make_uint2(l0, l1);
    }
}

// 128x64 fp32 tile (row stride NW) -> bf16 planes, rows of 128B, XOR-16B swizzle
__device__ __forceinline__ void x_tile_sts(char* sm, uint32_t oh, uint32_t ol,
                                           const float* __restrict__ xb, int tid) {
    #pragma unroll
    for (int it = 0; it < 8; it++) {
        int idx = tid * 4 + it * 1024;
        int k = idx >> 6, n = idx & 63;
        float4 v = *(const float4*)(xb + (size_t)k * NW + n);
        uint32_t h0, l0, h1, l1;
        bf16_split2(v.x, v.y, h0, l0);
        bf16_split2(v.z, v.w, h1, l1);
        uint32_t byte = (uint32_t)(k * 128) + (((uint32_t)(n * 2)) ^ (((uint32_t)k & 7) << 4));
        *(uint2*)(sm + oh + byte) = make_uint2(h0, h1);
        *(uint2*)(sm + ol + byte) = make_uint2(l0, l1);
    }
}

// ---------------------------------------------------------------------------
__global__ void k_zero() {
    int i = blockIdx.x * blockDim.x + threadIdx.x;   // 66*1024 = 65536 + 2048
    if (i < NB * 4096) g_S[i] = 0.0f;
    else g_Z[i - NB * 4096] = 0.0f;
}

// ---------------------------------------------------------------------------
// kv = W_kv @ x via HMMA (bf16x3); epilogue: ek=exp(k), Z atomics, S += ek@v^T
// smem: Whi [0,64K), Wlo [64K,128K), x planes @128K/+16K (inside sEk/sV region)
// sEk fp32 @131072 (128x68), sV @165888 (128x68); total 200704
__global__ void __launch_bounds__(256, 1)
k_kvctx(const float* __restrict__ x, const float* __restrict__ Wqkv) {
    extern __shared__ char sm[];
    const uint32_t smb = smem_u32(sm);
    float* sEk = (float*)(sm + 131072);
    float* sV  = (float*)(sm + 165888);
    const int tid = threadIdx.x, wid = tid >> 5, lane = tid & 31;
    const int mbase = wid * 32;

    w_row_sts(sm, 0u, 65536u, Wqkv + 128 * 128, 256, tid);

    for (int tile = blockIdx.x; tile < NTILES; tile += GRID_SM) {
        int b = tile >> 8, n0 = (tile & 255) * 64;
        __syncthreads();   // W ready / prior epilogue reads done
        x_tile_sts(sm, 131072u, 147456u, x + (size_t)b * NCH * NW + n0, tid);
        __syncthreads();

        float C[2][8][4];
        #pragma unroll
        for (int i = 0; i < 2; i++)
            #pragma unroll
            for (int j = 0; j < 8; j++)
                #pragma unroll
                for (int q = 0; q < 4; q++) C[i][j][q] = 0.0f;

        #pragma unroll
        for (int pass = 0; pass < 3; pass++) {
            uint32_t Ab = smb + (pass == 2 ? 65536u : 0u);
            uint32_t Bb = smb + 131072u + (pass == 1 ? 16384u : 0u);
            #pragma unroll
            for (int ks = 0; ks < 8; ks++) {
                int k0 = ks * 16;
                uint32_t a[2][4], bfr[4][4];
                #pragma unroll
                for (int mt = 0; mt < 2; mt++) {
                    int row = mbase + mt * 16 + (lane & 15);
                    uint32_t kb = (uint32_t)((k0 + ((lane >> 4) << 3)) * 2);
                    ldsm_x4(a[mt], Ab + (uint32_t)(row * 256) + (kb ^ (((uint32_t)row & 7) << 4)));
                }
                #pragma unroll
                for (int t2 = 0; t2 < 4; t2++) {
                    int krow = k0 + (lane & 15);
                    uint32_t nb = (uint32_t)((t2 * 16 + ((lane >> 4) << 3)) * 2);
                    ldsm_x4t(bfr[t2], Bb + (uint32_t)(krow * 128) + (nb ^ (((uint32_t)krow & 7) << 4)));
                }
                #pragma unroll
                for (int mt = 0; mt < 2; mt++)
                    #pragma unroll
                    for (int t2 = 0; t2 < 4; t2++) {
                        mma16816(C[mt][t2 * 2],     a[mt], &bfr[t2][0]);
                        mma16816(C[mt][t2 * 2 + 1], a[mt], &bfr[t2][2]);
                    }
            }
        }
        __syncthreads();   // all x-plane reads done before overwrite

        if (wid < 4) {     // k rows -> exp -> sEk
            #pragma unroll
            for (int mt = 0; mt < 2; mt++)
                #pragma unroll
                for (int nt = 0; nt < 8; nt++) {
                    int r0 = mbase + mt * 16 + (lane >> 2);
                    int cc = nt * 8 + 2 * (lane & 3);
                    *(float2*)(sEk + r0 * 68 + cc) =
                        make_float2(__expf(C[mt][nt][0]), __expf(C[mt][nt][1]));
                    *(float2*)(sEk + (r0 + 8) * 68 + cc) =
                        make_float2(__expf(C[mt][nt][2]), __expf(C[mt][nt][3]));
                }
        } else {           // v rows -> sV
            #pragma unroll
            for (int mt = 0; mt < 2; mt++)
                #pragma unroll
                for (int nt = 0; nt < 8; nt++) {
                    int r0 = mbase - 128 + mt * 16 + (lane >> 2);
                    int cc = nt * 8 + 2 * (lane & 3);
                    *(float2*)(sV + r0 * 68 + cc) = make_float2(C[mt][nt][0], C[mt][nt][1]);
                    *(float2*)(sV + (r0 + 8) * 68 + cc) = make_float2(C[mt][nt][2], C[mt][nt][3]);
                }
        }
        __syncthreads();

        if (tid < 128) {
            float z = 0.0f;
            #pragma unroll 8
            for (int n = 0; n < 64; n++) z += sEk[tid * 68 + n];
            atomicAdd(g_Z + b * 128 + tid, z);
        }
        {   // S accumulation (fp32)
            int h = tid >> 6, rem = tid & 63;
            int dblk = rem >> 3, eblk = rem & 7;
            const float* ekp = sEk + (h * 32 + dblk * 4) * 68;
            const float* vp  = sV  + (h * 32 + eblk * 4) * 68;
            float s[4][4];
            #pragma unroll
            for (int a2 = 0; a2 < 4; a2++)
                #pragma unroll
                for (int b2 = 0; b2 < 4; b2++) s[a2][b2] = 0.0f;
            #pragma unroll 4
            for (int n = 0; n < 64; n += 4) {
                float4 e[4], vv[4];
                #pragma unroll
                for (int a2 = 0; a2 < 4; a2++) e[a2] = *(const float4*)(ekp + a2 * 68 + n);
                #pragma unroll
                for (int b2 = 0; b2 < 4; b2++) vv[b2] = *(const float4*)(vp + b2 * 68 + n);
                #pragma unroll
                for (int a2 = 0; a2 < 4; a2++)
                    #pragma unroll
                    for (int b2 = 0; b2 < 4; b2++)
                        s[a2][b2] += e[a2].x * vv[b2].x + e[a2].y * vv[b2].y
                                   + e[a2].z * vv[b2].z + e[a2].w * vv[b2].w;
            }
            float* gS = g_S + b * 4096 + h * 1024 + dblk * 128 + eblk * 4;
            #pragma unroll
            for (int a2 = 0; a2 < 4; a2++)
                #pragma unroll
                for (int b2 = 0; b2 < 4; b2++)
                    atomicAdd(gS + a2 * 32 + b2, s[a2][b2]);
        }
    }
}

// ---------------------------------------------------------------------------
__global__ void k_mbuild(const float* __restrict__ Wout) {
    __shared__ float sCtx[4096];
    __shared__ float sWo[16 * 128];
    int b = blockIdx.y, o0 = blockIdx.x * 16;
    int tid = threadIdx.x;
    for (int idx = tid * 4; idx < 4096; idx += 1024) {
        float4 sv = *(const float4*)(g_S + b * 4096 + idx);
        float z = g_Z[b * 128 + (idx >> 5)];
        float r = 1.0f / (z * (float)NW);
        sv.x *= r; sv.y *= r; sv.z *= r; sv.w *= r;
        *(float4*)(sCtx + idx) = sv;
    }
    for (int idx = tid * 4; idx < 2048; idx += 1024)
        *(float4*)(sWo + idx) = *(const float4*)(Wout + (size_t)o0 * 128 + idx);
    __syncthreads();
    for (int idx = tid; idx < 2048; idx += 256) {
        int orr = idx >> 7, hd = idx & 127;
        int h = hd >> 5, d = hd & 31;
        const float* wrow = sWo + orr * 128 + h * 32;
        const float* crow = sCtx + h * 1024 + d * 32;
        float sum = 0.0f;
        #pragma unroll
        for (int e4 = 0; e4 < 8; e4++) {
            float4 w4 = *(const float4*)(wrow + e4 * 4);
            float4 c4 = *(const float4*)(crow + e4 * 4);
            sum += w4.x * c4.x + w4.y * c4.y + w4.z * c4.z + w4.w * c4.w;
        }
        g_M[b * 16384 + (o0 + orr) * 128 + hd] = SCALE_F * sum;
    }
}

// ---------------------------------------------------------------------------
// q = W_q @ x (HMMA); head-softmax in frags; y = M_b @ qsm (HMMA); bias+LN
// smem: Wq hi/lo [0,64K), M hi/lo [64K,128K), x/qsm planes @128K/+16K, sY @163840
__global__ void __launch_bounds__(256, 1)
k_qout(const float* __restrict__ x, const float* __restrict__ Wqkv,
       const float* __restrict__ b_out, const float* __restrict__ gamma,
       const float* __restrict__ beta, float* __restrict__ out) {
    extern __shared__ char sm[];
    __shared__ float sBias[128], sGamma[128], sBeta[128], sStat[128];
    const uint32_t smb = smem_u32(sm);
    float* sY = (float*)(sm + 163840);
    const int tid = threadIdx.x, wid = tid >> 5, lane = tid & 31;
    const int mbase = (wid >> 1) * 32;
    const int nbase = (wid & 1) * 32;

    w_row_sts(sm, 0u, 32768u, Wqkv, 128, tid);
    if (tid < 128) {
        sBias[tid] = b_out[tid]; sGamma[tid] = gamma[tid]; sBeta[tid] = beta[tid];
    }

    int per = (NTILES + GRID_SM - 1) / GRID_SM;
    int lo = blockIdx.x * per, hi = min(NTILES, lo + per);
    int curb = -1;

    for (int tile = lo; tile < hi; tile++) {
        int b = tile >> 8, n0 = (tile & 255) * 64;
        if (b != curb) {
            __syncthreads();
            w_row_sts(sm, 65536u, 98304u, g_M + (size_t)b * 16384, 128, tid);
            curb = b;
        }
        __syncthreads();
        x_tile_sts(sm, 131072u, 147456u, x + (size_t)b * NCH * NW + n0, tid);
        __syncthreads();

        float C[2][4][4];
        // ---- GEMM helper macro (Abase0 selects Wq or M planes) ----
        #define DO_GEMM(ABASE0)                                                          \
        do {                                                                             \
            _Pragma("unroll")                                                            \
            for (int i = 0; i < 2; i++)                                                  \
                _Pragma("unroll")                                                        \
                for (int j = 0; j < 4; j++)                                              \
                    _Pragma("unroll")                                                    \
                    for (int q = 0; q < 4; q++) C[i][j][q] = 0.0f;                       \
            _Pragma("unroll")                                                            \
            for (int pass = 0; pass < 3; pass++) {                                       \
                uint32_t Ab = smb + (ABASE0) + (pass == 2 ? 32768u : 0u);                \
                uint32_t Bb = smb + 131072u + (pass == 1 ? 16384u : 0u);                 \
                _Pragma("unroll")                                                        \
                for (int ks = 0; ks < 8; ks++) {                                         \
                    int k0 = ks * 16;                                                    \
                    uint32_t a[2][4], bfr[2][4];                                         \
                    _Pragma("unroll")                                                    \
                    for (int mt = 0; mt < 2; mt++) {                                     \
                        int row = mbase + mt * 16 + (lane & 15);                         \
                        uint32_t kb = (uint32_t)((k0 + ((lane >> 4) << 3)) * 2);         \
                        ldsm_x4(a[mt], Ab + (uint32_t)(row * 256)                        \
                                + (kb ^ (((uint32_t)row & 7) << 4)));                    \
                    }                                                                    \
                    _Pragma("unroll")                                                    \
                    for (int t2 = 0; t2 < 2; t2++) {                                     \
                        int krow = k0 + (lane & 15);                                     \
                        uint32_t nb = (uint32_t)((nbase * 2)                             \
                                + (t2 * 16 + ((lane >> 4) << 3)) * 2);                   \
                        ldsm_x4t(bfr[t2], Bb + (uint32_t)(krow * 128)                    \
                                + (nb ^ (((uint32_t)krow & 7) << 4)));                   \
                    }                                                                    \
                    _Pragma("unroll")                                                    \
                    for (int mt = 0; mt < 2; mt++)                                       \
                        _Pragma("unroll")                                                \
                        for (int t2 = 0; t2 < 2; t2++) {                                 \
                            mma16816(C[mt][t2 * 2],     a[mt], &bfr[t2][0]);             \
                            mma16816(C[mt][t2 * 2 + 1], a[mt], &bfr[t2][2]);             \
                        }                                                                \
                }                                                                        \
            }                                                                            \
        } while (0)

        DO_GEMM(0u);           // q = W_q @ x
        __syncthreads();       // x-plane reads done before qsm overwrite

        {   // softmax over head-dim (warp rows = one head)
            #pragma unroll
            for (int nt = 0; nt < 4; nt++) {
                float p0 = 0.0f, p1 = 0.0f;
                #pragma unroll
                for (int mt = 0; mt < 2; mt++) {
                    #pragma unroll
                    for (int q = 0; q < 4; q++) C[mt][nt][q] = __expf(C[mt][nt][q]);
                    p0 += C[mt][nt][0] + C[mt][nt][2];
                    p1 += C[mt][nt][1] + C[mt][nt][3];
                }
                p0 += __shfl_xor_sync(0xFFFFFFFFu, p0, 4);
                p0 += __shfl_xor_sync(0xFFFFFFFFu, p0, 8);
                p0 += __shfl_xor_sync(0xFFFFFFFFu, p0, 16);
                p1 += __shfl_xor_sync(0xFFFFFFFFu, p1, 4);
                p1 += __shfl_xor_sync(0xFFFFFFFFu, p1, 8);
                p1 += __shfl_xor_sync(0xFFFFFFFFu, p1, 16);
                float r0 = __fdividef(1.0f, p0), r1 = __fdividef(1.0f, p1);
                #pragma unroll
                for (int mt = 0; mt < 2; mt++) {
                    C[mt][nt][0] *= r0; C[mt][nt][2] *= r0;
                    C[mt][nt][1] *= r1; C[mt][nt][3] *= r1;
                }
            }
            // write qsm bf16 planes over x region
            #pragma unroll
            for (int mt = 0; mt < 2; mt++)
                #pragma unroll
                for (int nt = 0; nt < 4; nt++) {
                    int r0 = mbase + mt * 16 + (lane >> 2);
                    int cc = nbase + nt * 8 + 2 * (lane & 3);
                    uint32_t h, l;
                    bf16_split2(C[mt][nt][0], C[mt][nt][1], h, l);
                    uint32_t byte = (uint32_t)(r0 * 128)
                                  + (((uint32_t)(cc * 2)) ^ (((uint32_t)r0 & 7) << 4));
                    *(uint32_t*)(sm + 131072 + byte) = h;
                    *(uint32_t*)(sm + 147456 + byte) = l;
                    int r1 = r0 + 8;
                    bf16_split2(C[mt][nt][2], C[mt][nt][3], h, l);
                    byte = (uint32_t)(r1 * 128)
                         + (((uint32_t)(cc * 2)) ^ (((uint32_t)r1 & 7) << 4));
                    *(uint32_t*)(sm + 131072 + byte) = h;
                    *(uint32_t*)(sm + 147456 + byte) = l;
                }
        }
        __syncthreads();

        DO_GEMM(65536u);       // y = M_b @ qsm
        #undef DO_GEMM

        {   // +bias, store fp32 to sY
            #pragma unroll
            for (int mt = 0; mt < 2; mt++)
                #pragma unroll
                for (int nt = 0; nt < 4; nt++) {
                    int r0 = mbase + mt * 16 + (lane >> 2);
                    int cc = nbase + nt * 8 + 2 * (lane & 3);
                    float b0 = sBias[r0], b1 = sBias[r0 + 8];
                    *(float2*)(sY + r0 * 68 + cc) =
                        make_float2(C[mt][nt][0] + b0, C[mt][nt][1] + b0);
                    *(float2*)(sY + (r0 + 8) * 68 + cc) =
                        make_float2(C[mt][nt][2] + b1, C[mt][nt][3] + b1);
                }
        }
        __syncthreads();
        if (tid < 64) {   // LN stats per column
            float s = 0.0f, sq = 0.0f;
            #pragma unroll 8
            for (int rr = 0; rr < 128; rr++) {
                float v = sY[rr * 68 + tid];
                s += v; sq += v * v;
            }
            float mean = s * (1.0f / 128.0f);
            float var = sq * (1.0f / 128.0f) - mean * mean;
            sStat[tid * 2] = mean;
            sStat[tid * 2 + 1] = rsqrtf(var + LN_EPS);
        }
        __syncthreads();
        float* ob = out + (size_t)b * NCH * NW + n0;
        for (int idx = tid * 4; idx < 8192; idx += 1024) {
            int rr = idx >> 6, cc = idx & 63;
            float4 v = *(const float4*)(sY + rr * 68 + cc);
            float g = sGamma[rr], be = sBeta[rr];
            v.x = (v.x - sStat[2 * cc])       * sStat[2 * cc + 1]       * g + be;
            v.y = (v.y - sStat[2 * (cc + 1)]) * sStat[2 * (cc + 1) + 1] * g + be;
            v.z = (v.z - sStat[2 * (cc + 2)]) * sStat[2 * (cc + 2) + 1] * g + be;
            v.w = (v.w - sStat[2 * (cc + 3)]) * sStat[2 * (cc + 3) + 1] * g + be;
            *(float4*)(ob + (size_t)rr * NW + cc) = v;
        }
    }
}

// ---------------------------------------------------------------------------
extern "C" void kernel_launch(void* const* d_in, const int* in_sizes, int n_in,
                              void* d_out, int out_size) {
    const float* x    = (const float*)d_in[0];
    const float* Wqkv = (const float*)d_in[1];
    const float* Wout = (const float*)d_in[2];
    const float* bo   = (const float*)d_in[3];
    const float* gm   = (const float*)d_in[4];
    const float* bt   = (const float*)d_in[5];
    float* out = (float*)d_out;

    const int SMEM_A = 200704;
    const int SMEM_C = 198656;
    cudaFuncSetAttribute(k_kvctx, cudaFuncAttributeMaxDynamicSharedMemorySize, SMEM_A);
    cudaFuncSetAttribute(k_qout,  cudaFuncAttributeMaxDynamicSharedMemorySize, SMEM_C);

    k_zero<<<66, 1024>>>();
    k_kvctx<<<GRID_SM, 256, SMEM_A>>>(x, Wqkv);
    k_mbuild<<<dim3(8, 16), 256>>>(Wout);
    k_qout<<<GRID_SM, 256, SMEM_C>>>(x, Wqkv, bo, gm, bt, out);
}

// round 8
// speedup vs baseline: 1.8179x; 1.0109x over previous
#include <cuda_runtime.h>
#include <cstdint>

#define NB 16
#define NCH 128
#define NW 16384
#define NTILES 4096
#define GRID_SM 152
#define SCALE_F 0.17677669529663687f
#define LN_EPS 1e-5f

__device__ float g_S[NB * 4096];
__device__ float g_Z[NB * 128];
__device__ float g_M[NB * 128 * 128];

__device__ __forceinline__ uint32_t smem_u32(const void* p) {
    uint32_t a;
    asm("{ .reg .u64 t; cvta.to.shared.u64 t, %1; cvt.u32.u64 %0, t; }" : "=r"(a) : "l"(p));
    return a;
}
__device__ __forceinline__ void bf16_split2(float a, float b, uint32_t& h, uint32_t& l) {
    asm("cvt.rn.bf16x2.f32 %0, %1, %2;" : "=r"(h) : "f"(b), "f"(a));
    float ra = a - __uint_as_float(h << 16);
    float rb = b - __uint_as_float(h & 0xFFFF0000u);
    asm("cvt.rn.bf16x2.f32 %0, %1, %2;" : "=r"(l) : "f"(rb), "f"(ra));
}
__device__ __forceinline__ void ldsm_x4(uint32_t* a, uint32_t addr) {
    asm volatile("ldmatrix.sync.aligned.m8n8.x4.shared.b16 {%0,%1,%2,%3}, [%4];"
                 : "=r"(a[0]), "=r"(a[1]), "=r"(a[2]), "=r"(a[3]) : "r"(addr));
}
__device__ __forceinline__ void ldsm_x4t(uint32_t* a, uint32_t addr) {
    asm volatile("ldmatrix.sync.aligned.m8n8.x4.trans.shared.b16 {%0,%1,%2,%3}, [%4];"
                 : "=r"(a[0]), "=r"(a[1]), "=r"(a[2]), "=r"(a[3]) : "r"(addr));
}
__device__ __forceinline__ void mma16816(float* c, const uint32_t* a, const uint32_t* b) {
    asm volatile("mma.sync.aligned.m16n8k16.row.col.f32.bf16.bf16.f32 "
                 "{%0,%1,%2,%3},{%4,%5,%6,%7},{%8,%9},{%0,%1,%2,%3};"
                 : "+f"(c[0]), "+f"(c[1]), "+f"(c[2]), "+f"(c[3])
                 : "r"(a[0]), "r"(a[1]), "r"(a[2]), "r"(a[3]), "r"(b[0]), "r"(b[1]));
}

// fp32 row of 128 -> two bf16 planes in smem, rows of 256B, XOR-16B swizzle
__device__ __forceinline__ void w_row_sts(char* sm, uint32_t oh, uint32_t ol,
                                          const float* __restrict__ src,
                                          int nrows, int tid) {
    for (int i = 0; i < nrows * 32; i += 256) {
        int idx = (tid + i) * 4;
        int m = idx >> 7, k = idx & 127;
        float4 w = *(const float4*)(src + m * 128 + k);
        uint32_t h0, l0, h1, l1;
        bf16_split2(w.x, w.y, h0, l0);
        bf16_split2(w.z, w.w, h1, l1);
        uint32_t byte = (uint32_t)(m * 256) + (((uint32_t)(k * 2)) ^ (((uint32_t)m & 7) << 4));
        *(uint2*)(sm + oh + byte) = make_uint2(h0, h1);
        *(uint2*)(sm + ol + byte) = make_uint2(l0, l1);
    }
}

// 128x64 fp32 tile (row stride NW) -> bf16 planes, rows of 128B, XOR-16B swizzle
__device__ __forceinline__ void x_tile_sts(char* sm, uint32_t oh, uint32_t ol,
                                           const float* __restrict__ xb, int tid) {
    #pragma unroll
    for (int it = 0; it < 8; it++) {
        int idx = tid * 4 + it * 1024;
        int k = idx >> 6, n = idx & 63;
        float4 v = *(const float4*)(xb + (size_t)k * NW + n);
        uint32_t h0, l0, h1, l1;
        bf16_split2(v.x, v.y, h0, l0);
        bf16_split2(v.z, v.w, h1, l1);
        uint32_t byte = (uint32_t)(k * 128) + (((uint32_t)(n * 2)) ^ (((uint32_t)k & 7) << 4));
        *(uint2*)(sm + oh + byte) = make_uint2(h0, h1);
        *(uint2*)(sm + ol + byte) = make_uint2(l0, l1);
    }
}

// ---------------------------------------------------------------------------
__global__ void k_zero() {
    int i = blockIdx.x * blockDim.x + threadIdx.x;
    if (i < NB * 4096) g_S[i] = 0.0f;
    else g_Z[i - NB * 4096] = 0.0f;
}

// ---------------------------------------------------------------------------
// kv = W_kv @ x (HMMA bf16x3); epilogue: ek=exp(k)->sEk, v->sV (fp32);
// S,Z accumulate in REGISTERS across a contiguous tile chunk, flushed per batch.
// smem: Whi [0,64K), Wlo [64K,128K), x planes @128K/+16K (inside sEk/sV region)
// sEk fp32 @131072 (128x68), sV @165888 (128x68); total 200704
__global__ void __launch_bounds__(256, 1)
k_kvctx(const float* __restrict__ x, const float* __restrict__ Wqkv) {
    extern __shared__ char sm[];
    const uint32_t smb = smem_u32(sm);
    float* sEk = (float*)(sm + 131072);
    float* sV  = (float*)(sm + 165888);
    const int tid = threadIdx.x, wid = tid >> 5, lane = tid & 31;
    const int mbase = wid * 32;

    w_row_sts(sm, 0u, 65536u, Wqkv + 128 * 128, 256, tid);

    int per = (NTILES + GRID_SM - 1) / GRID_SM;   // 27
    int lo = blockIdx.x * per, hi = min(NTILES, lo + per);

    // S-accumulation thread mapping (fixed per thread, same as R4)
    const int sh   = tid >> 6;
    const int srem = tid & 63;
    const int sdblk = srem >> 3, seblk = srem & 7;

    float sreg[4][4];
    float zreg = 0.0f;
    int curb = -1;

    float4 px[8];
    if (lo < hi) {
        const float* xb = x + (size_t)(lo >> 8) * NCH * NW + (size_t)(lo & 255) * 64;
        #pragma unroll
        for (int it = 0; it < 8; it++) {
            int idx = tid * 4 + it * 1024;
            px[it] = *(const float4*)(xb + (size_t)(idx >> 6) * NW + (idx & 63));
        }
    }

    for (int tile = lo; tile < hi; tile++) {
        int b = tile >> 8;
        if (b != curb) {
            if (curb >= 0) {   // flush previous batch
                float* gS = g_S + curb * 4096 + sh * 1024 + sdblk * 128 + seblk * 4;
                #pragma unroll
                for (int a2 = 0; a2 < 4; a2++)
                    #pragma unroll
                    for (int b2 = 0; b2 < 4; b2++)
                        atomicAdd(gS + a2 * 32 + b2, sreg[a2][b2]);
                if (tid < 128) atomicAdd(g_Z + curb * 128 + tid, zreg);
            }
            #pragma unroll
            for (int a2 = 0; a2 < 4; a2++)
                #pragma unroll
                for (int b2 = 0; b2 < 4; b2++) sreg[a2][b2] = 0.0f;
            zreg = 0.0f;
            curb = b;
        }

        __syncthreads();   // W staged (1st iter) / prior S-phase reads of sEk/sV done
        // STS x from prefetched regs
        #pragma unroll
        for (int it = 0; it < 8; it++) {
            int idx = tid * 4 + it * 1024;
            int k = idx >> 6, n = idx & 63;
            uint32_t h0, l0, h1, l1;
            bf16_split2(px[it].x, px[it].y, h0, l0);
            bf16_split2(px[it].z, px[it].w, h1, l1);
            uint32_t byte = (uint32_t)(k * 128) + (((uint32_t)(n * 2)) ^ (((uint32_t)k & 7) << 4));
            *(uint2*)(sm + 131072u + byte) = make_uint2(h0, h1);
            *(uint2*)(sm + 147456u + byte) = make_uint2(l0, l1);
        }
        // prefetch next tile into registers
        if (tile + 1 < hi) {
            int nt2 = tile + 1;
            const float* xb = x + (size_t)(nt2 >> 8) * NCH * NW + (size_t)(nt2 & 255) * 64;
            #pragma unroll
            for (int it = 0; it < 8; it++) {
                int idx = tid * 4 + it * 1024;
                px[it] = *(const float4*)(xb + (size_t)(idx >> 6) * NW + (idx & 63));
            }
        }
        __syncthreads();

        // main GEMM: kv(256x64) = W_kv @ x, bf16x3
        float C[2][8][4];
        #pragma unroll
        for (int i = 0; i < 2; i++)
            #pragma unroll
            for (int j = 0; j < 8; j++)
                #pragma unroll
                for (int q = 0; q < 4; q++) C[i][j][q] = 0.0f;

        #pragma unroll
        for (int pass = 0; pass < 3; pass++) {
            uint32_t Ab = smb + (pass == 2 ? 65536u : 0u);
            uint32_t Bb = smb + 131072u + (pass == 1 ? 16384u : 0u);
            #pragma unroll
            for (int ks = 0; ks < 8; ks++) {
                int k0 = ks * 16;
                uint32_t a[2][4], bfr[4][4];
                #pragma unroll
                for (int mt = 0; mt < 2; mt++) {
                    int row = mbase + mt * 16 + (lane & 15);
                    uint32_t kb = (uint32_t)((k0 + ((lane >> 4) << 3)) * 2);
                    ldsm_x4(a[mt], Ab + (uint32_t)(row * 256) + (kb ^ (((uint32_t)row & 7) << 4)));
                }
                #pragma unroll
                for (int t2 = 0; t2 < 4; t2++) {
                    int krow = k0 + (lane & 15);
                    uint32_t nb = (uint32_t)((t2 * 16 + ((lane >> 4) << 3)) * 2);
                    ldsm_x4t(bfr[t2], Bb + (uint32_t)(krow * 128) + (nb ^ (((uint32_t)krow & 7) << 4)));
                }
                #pragma unroll
                for (int mt = 0; mt < 2; mt++)
                    #pragma unroll
                    for (int t2 = 0; t2 < 4; t2++) {
                        mma16816(C[mt][t2 * 2],     a[mt], &bfr[t2][0]);
                        mma16816(C[mt][t2 * 2 + 1], a[mt], &bfr[t2][2]);
                    }
            }
        }
        __syncthreads();   // all x-plane reads done before sEk overwrite

        if (wid < 4) {     // k rows -> exp -> sEk (fp32)
            #pragma unroll
            for (int mt = 0; mt < 2; mt++)
                #pragma unroll
                for (int nt = 0; nt < 8; nt++) {
                    int r0 = mbase + mt * 16 + (lane >> 2);
                    int cc = nt * 8 + 2 * (lane & 3);
                    *(float2*)(sEk + r0 * 68 + cc) =
                        make_float2(__expf(C[mt][nt][0]), __expf(C[mt][nt][1]));
                    *(float2*)(sEk + (r0 + 8) * 68 + cc) =
                        make_float2(__expf(C[mt][nt][2]), __expf(C[mt][nt][3]));
                }
        } else {           // v rows -> sV (fp32)
            #pragma unroll
            for (int mt = 0; mt < 2; mt++)
                #pragma unroll
                for (int nt = 0; nt < 8; nt++) {
                    int r0 = mbase - 128 + mt * 16 + (lane >> 2);
                    int cc = nt * 8 + 2 * (lane & 3);
                    *(float2*)(sV + r0 * 68 + cc) = make_float2(C[mt][nt][0], C[mt][nt][1]);
                    *(float2*)(sV + (r0 + 8) * 68 + cc) = make_float2(C[mt][nt][2], C[mt][nt][3]);
                }
        }
        __syncthreads();

        // Z: per-row sums into register
        if (tid < 128) {
            float z = 0.0f;
            #pragma unroll 8
            for (int n = 0; n < 64; n++) z += sEk[tid * 68 + n];
            zreg += z;
        }
        // S: fp32 outer-product accumulated into registers
        {
            const float* ekp = sEk + (sh * 32 + sdblk * 4) * 68;
            const float* vp  = sV  + (sh * 32 + seblk * 4) * 68;
            #pragma unroll 4
            for (int n = 0; n < 64; n += 4) {
                float4 e[4], vv[4];
                #pragma unroll
                for (int a2 = 0; a2 < 4; a2++) e[a2] = *(const float4*)(ekp + a2 * 68 + n);
                #pragma unroll
                for (int b2 = 0; b2 < 4; b2++) vv[b2] = *(const float4*)(vp + b2 * 68 + n);
                #pragma unroll
                for (int a2 = 0; a2 < 4; a2++)
                    #pragma unroll
                    for (int b2 = 0; b2 < 4; b2++)
                        sreg[a2][b2] += e[a2].x * vv[b2].x + e[a2].y * vv[b2].y
                                      + e[a2].z * vv[b2].z + e[a2].w * vv[b2].w;
            }
        }
    }

    // final flush
    if (curb >= 0) {
        float* gS = g_S + curb * 4096 + sh * 1024 + sdblk * 128 + seblk * 4;
        #pragma unroll
        for (int a2 = 0; a2 < 4; a2++)
            #pragma unroll
            for (int b2 = 0; b2 < 4; b2++)
                atomicAdd(gS + a2 * 32 + b2, sreg[a2][b2]);
        if (tid < 128) atomicAdd(g_Z + curb * 128 + tid, zreg);
    }
}

// ---------------------------------------------------------------------------
__global__ void k_mbuild(const float* __restrict__ Wout) {
    __shared__ float sCtx[4096];
    __shared__ float sWo[16 * 128];
    int b = blockIdx.y, o0 = blockIdx.x * 16;
    int tid = threadIdx.x;
    for (int idx = tid * 4; idx < 4096; idx += 1024) {
        float4 sv = *(const float4*)(g_S + b * 4096 + idx);
        float z = g_Z[b * 128 + (idx >> 5)];
        float r = 1.0f / (z * (float)NW);
        sv.x *= r; sv.y *= r; sv.z *= r; sv.w *= r;
        *(float4*)(sCtx + idx) = sv;
    }
    for (int idx = tid * 4; idx < 2048; idx += 1024)
        *(float4*)(sWo + idx) = *(const float4*)(Wout + (size_t)o0 * 128 + idx);
    __syncthreads();
    for (int idx = tid; idx < 2048; idx += 256) {
        int orr = idx >> 7, hd = idx & 127;
        int hh = hd >> 5, d = hd & 31;
        const float* wrow = sWo + orr * 128 + hh * 32;
        const float* crow = sCtx + hh * 1024 + d * 32;
        float sum = 0.0f;
        #pragma unroll
        for (int e4 = 0; e4 < 8; e4++) {
            float4 w4 = *(const float4*)(wrow + e4 * 4);
            float4 c4 = *(const float4*)(crow + e4 * 4);
            sum += w4.x * c4.x + w4.y * c4.y + w4.z * c4.z + w4.w * c4.w;
        }
        g_M[b * 16384 + (o0 + orr) * 128 + hd] = SCALE_F * sum;
    }
}

// ---------------------------------------------------------------------------
// q = W_q @ x (HMMA); head-softmax in frags; y = M_b @ qsm (HMMA); bias+LN
__global__ void __launch_bounds__(256, 1)
k_qout(const float* __restrict__ x, const float* __restrict__ Wqkv,
       const float* __restrict__ b_out, const float* __restrict__ gamma,
       const float* __restrict__ beta, float* __restrict__ out) {
    extern __shared__ char sm[];
    __shared__ float sBias[128], sGamma[128], sBeta[128], sStat[128];
    __shared__ float sPS[256], sPQ[256];
    const uint32_t smb = smem_u32(sm);
    float* sY = (float*)(sm + 163840);
    const int tid = threadIdx.x, wid = tid >> 5, lane = tid & 31;
    const int mbase = (wid >> 1) * 32;
    const int nbase = (wid & 1) * 32;

    w_row_sts(sm, 0u, 32768u, Wqkv, 128, tid);
    if (tid < 128) {
        sBias[tid] = b_out[tid]; sGamma[tid] = gamma[tid]; sBeta[tid] = beta[tid];
    }

    int per = (NTILES + GRID_SM - 1) / GRID_SM;
    int lo = blockIdx.x * per, hi = min(NTILES, lo + per);
    int curb = -1;

    for (int tile = lo; tile < hi; tile++) {
        int b = tile >> 8, n0 = (tile & 255) * 64;
        if (b != curb) {
            __syncthreads();
            w_row_sts(sm, 65536u, 98304u, g_M + (size_t)b * 16384, 128, tid);
            curb = b;
        }
        __syncthreads();
        x_tile_sts(sm, 131072u, 147456u, x + (size_t)b * NCH * NW + n0, tid);
        __syncthreads();

        float C[2][4][4];
        #define DO_GEMM(ABASE0)                                                          \
        do {                                                                             \
            _Pragma("unroll")                                                            \
            for (int i = 0; i < 2; i++)                                                  \
                _Pragma("unroll")                                                        \
                for (int j = 0; j < 4; j++)                                              \
                    _Pragma("unroll")                                                    \
                    for (int q = 0; q < 4; q++) C[i][j][q] = 0.0f;                       \
            _Pragma("unroll")                                                            \
            for (int pass = 0; pass < 3; pass++) {                                       \
                uint32_t Ab = smb + (ABASE0) + (pass == 2 ? 32768u : 0u);                \
                uint32_t Bb = smb + 131072u + (pass == 1 ? 16384u : 0u);                 \
                _Pragma("unroll")                                                        \
                for (int ks = 0; ks < 8; ks++) {                                         \
                    int k0 = ks * 16;                                                    \
                    uint32_t a[2][4], bfr[2][4];                                         \
                    _Pragma("unroll")                                                    \
                    for (int mt = 0; mt < 2; mt++) {                                     \
                        int row = mbase + mt * 16 + (lane & 15);                         \
                        uint32_t kb = (uint32_t)((k0 + ((lane >> 4) << 3)) * 2);         \
                        ldsm_x4(a[mt], Ab + (uint32_t)(row * 256)                        \
                                + (kb ^ (((uint32_t)row & 7) << 4)));                    \
                    }                                                                    \
                    _Pragma("unroll")                                                    \
                    for (int t2 = 0; t2 < 2; t2++) {                                     \
                        int krow = k0 + (lane & 15);                                     \
                        uint32_t nb = (uint32_t)((nbase * 2)                             \
                                + (t2 * 16 + ((lane >> 4) << 3)) * 2);                   \
                        ldsm_x4t(bfr[t2], Bb + (uint32_t)(krow * 128)                    \
                                + (nb ^ (((uint32_t)krow & 7) << 4)));                   \
                    }                                                                    \
                    _Pragma("unroll")                                                    \
                    for (int mt = 0; mt < 2; mt++)                                       \
                        _Pragma("unroll")                                                \
                        for (int t2 = 0; t2 < 2; t2++) {                                 \
                            mma16816(C[mt][t2 * 2],     a[mt], &bfr[t2][0]);             \
                            mma16816(C[mt][t2 * 2 + 1], a[mt], &bfr[t2][2]);             \
                        }                                                                \
                }                                                                        \
            }                                                                            \
        } while (0)

        DO_GEMM(0u);
        __syncthreads();

        {   // softmax over head-dim
            #pragma unroll
            for (int nt = 0; nt < 4; nt++) {
                float p0 = 0.0f, p1 = 0.0f;
                #pragma unroll
                for (int mt = 0; mt < 2; mt++) {
                    #pragma unroll
                    for (int q = 0; q < 4; q++) C[mt][nt][q] = __expf(C[mt][nt][q]);
                    p0 += C[mt][nt][0] + C[mt][nt][2];
                    p1 += C[mt][nt][1] + C[mt][nt][3];
                }
                p0 += __shfl_xor_sync(0xFFFFFFFFu, p0, 4);
                p0 += __shfl_xor_sync(0xFFFFFFFFu, p0, 8);
                p0 += __shfl_xor_sync(0xFFFFFFFFu, p0, 16);
                p1 += __shfl_xor_sync(0xFFFFFFFFu, p1, 4);
                p1 += __shfl_xor_sync(0xFFFFFFFFu, p1, 8);
                p1 += __shfl_xor_sync(0xFFFFFFFFu, p1, 16);
                float r0 = __fdividef(1.0f, p0), r1 = __fdividef(1.0f, p1);
                #pragma unroll
                for (int mt = 0; mt < 2; mt++) {
                    C[mt][nt][0] *= r0; C[mt][nt][2] *= r0;
                    C[mt][nt][1] *= r1; C[mt][nt][3] *= r1;
                }
            }
            #pragma unroll
            for (int mt = 0; mt < 2; mt++)
                #pragma unroll
                for (int nt = 0; nt < 4; nt++) {
                    int r0 = mbase + mt * 16 + (lane >> 2);
                    int cc = nbase + nt * 8 + 2 * (lane & 3);
                    uint32_t hh, ll;
                    bf16_split2(C[mt][nt][0], C[mt][nt][1], hh, ll);
                    uint32_t byte = (uint32_t)(r0 * 128)
                                  + (((uint32_t)(cc * 2)) ^ (((uint32_t)r0 & 7) << 4));
                    *(uint32_t*)(sm + 131072 + byte) = hh;
                    *(uint32_t*)(sm + 147456 + byte) = ll;
                    int r1 = r0 + 8;
                    bf16_split2(C[mt][nt][2], C[mt][nt][3], hh, ll);
                    byte = (uint32_t)(r1 * 128)
                         + (((uint32_t)(cc * 2)) ^ (((uint32_t)r1 & 7) << 4));
                    *(uint32_t*)(sm + 131072 + byte) = hh;
                    *(uint32_t*)(sm + 147456 + byte) = ll;
                }
        }
        __syncthreads();

        DO_GEMM(65536u);
        #undef DO_GEMM

        {
            #pragma unroll
            for (int mt = 0; mt < 2; mt++)
                #pragma unroll
                for (int nt = 0; nt < 4; nt++) {
                    int r0 = mbase + mt * 16 + (lane >> 2);
                    int cc = nbase + nt * 8 + 2 * (lane & 3);
                    float b0 = sBias[r0], b1 = sBias[r0 + 8];
                    *(float2*)(sY + r0 * 68 + cc) =
                        make_float2(C[mt][nt][0] + b0, C[mt][nt][1] + b0);
                    *(float2*)(sY + (r0 + 8) * 68 + cc) =
                        make_float2(C[mt][nt][2] + b1, C[mt][nt][3] + b1);
                }
        }
        __syncthreads();
        {   // LN stats: 256-thread partials over row quarters
            int c = tid & 63, qr = tid >> 6;
            float s = 0.0f, sq = 0.0f;
            #pragma unroll 8
            for (int rr = qr * 32; rr < qr * 32 + 32; rr++) {
                float v = sY[rr * 68 + c];
                s += v; sq += v * v;
            }
            sPS[qr * 64 + c] = s;
            sPQ[qr * 64 + c] = sq;
        }
        __syncthreads();
        if (tid < 64) {
            float s  = sPS[tid] + sPS[64 + tid] + sPS[128 + tid] + sPS[192 + tid];
            float sq = sPQ[tid] + sPQ[64 + tid] + sPQ[128 + tid] + sPQ[192 + tid];
            float mean = s * (1.0f / 128.0f);
            float var = sq * (1.0f / 128.0f) - mean * mean;
            sStat[tid * 2] = mean;
            sStat[tid * 2 + 1] = rsqrtf(var + LN_EPS);
        }
        __syncthreads();
        float* ob = out + (size_t)b * NCH * NW + n0;
        for (int idx = tid * 4; idx < 8192; idx += 1024) {
            int rr = idx >> 6, cc = idx & 63;
            float4 v = *(const float4*)(sY + rr * 68 + cc);
            float g = sGamma[rr], be = sBeta[rr];
            v.x = (v.x - sStat[2 * cc])       * sStat[2 * cc + 1]       * g + be;
            v.y = (v.y - sStat[2 * (cc + 1)]) * sStat[2 * (cc + 1) + 1] * g + be;
            v.z = (v.z - sStat[2 * (cc + 2)]) * sStat[2 * (cc + 2) + 1] * g + be;
            v.w = (v.w - sStat[2 * (cc + 3)]) * sStat[2 * (cc + 3) + 1] * g + be;
            *(float4*)(ob + (size_t)rr * NW + cc) = v;
        }
    }
}

// ---------------------------------------------------------------------------
extern "C" void kernel_launch(void* const* d_in, const int* in_sizes, int n_in,
                              void* d_out, int out_size) {
    const float* x    = (const float*)d_in[0];
    const float* Wqkv = (const float*)d_in[1];
    const float* Wout = (const float*)d_in[2];
    const float* bo   = (const float*)d_in[3];
    const float* gm   = (const float*)d_in[4];
    const float* bt   = (const float*)d_in[5];
    float* out = (float*)d_out;

    const int SMEM_A = 200704;
    const int SMEM_C = 198656;
    cudaFuncSetAttribute(k_kvctx, cudaFuncAttributeMaxDynamicSharedMemorySize, SMEM_A);
    cudaFuncSetAttribute(k_qout,  cudaFuncAttributeMaxDynamicSharedMemorySize, SMEM_C);

    k_zero<<<66, 1024>>>();
    k_kvctx<<<GRID_SM, 256, SMEM_A>>>(x, Wqkv);
    k_mbuild<<<dim3(8, 16), 256>>>(Wout);
    k_qout<<<GRID_SM, 256, SMEM_C>>>(x, Wqkv, bo, gm, bt, out);
}

// round 9
// speedup vs baseline: 2.2859x; 1.2574x over previous
#include <cuda_runtime.h>
#include <cstdint>

#define NB 16
#define NCH 128
#define NW 16384
#define NTILES 4096
#define GRID_SM 152
#define SCALE_F 0.17677669529663687f
#define LN_EPS 1e-5f

__device__ float g_S[NB * 4096];
__device__ float g_Z[NB * 128];
__device__ float g_M[NB * 128 * 128];

__device__ __forceinline__ uint32_t smem_u32(const void* p) {
    uint32_t a;
    asm("{ .reg .u64 t; cvta.to.shared.u64 t, %1; cvt.u32.u64 %0, t; }" : "=r"(a) : "l"(p));
    return a;
}
__device__ __forceinline__ void bf16_split2(float a, float b, uint32_t& h, uint32_t& l) {
    asm("cvt.rn.bf16x2.f32 %0, %1, %2;" : "=r"(h) : "f"(b), "f"(a));
    float ra = a - __uint_as_float(h << 16);
    float rb = b - __uint_as_float(h & 0xFFFF0000u);
    asm("cvt.rn.bf16x2.f32 %0, %1, %2;" : "=r"(l) : "f"(rb), "f"(ra));
}
__device__ __forceinline__ void ldsm_x4(uint32_t* a, uint32_t addr) {
    asm volatile("ldmatrix.sync.aligned.m8n8.x4.shared.b16 {%0,%1,%2,%3}, [%4];"
                 : "=r"(a[0]), "=r"(a[1]), "=r"(a[2]), "=r"(a[3]) : "r"(addr));
}
__device__ __forceinline__ void ldsm_x4t(uint32_t* a, uint32_t addr) {
    asm volatile("ldmatrix.sync.aligned.m8n8.x4.trans.shared.b16 {%0,%1,%2,%3}, [%4];"
                 : "=r"(a[0]), "=r"(a[1]), "=r"(a[2]), "=r"(a[3]) : "r"(addr));
}
__device__ __forceinline__ void mma16816(float* c, const uint32_t* a, const uint32_t* b) {
    asm volatile("mma.sync.aligned.m16n8k16.row.col.f32.bf16.bf16.f32 "
                 "{%0,%1,%2,%3},{%4,%5,%6,%7},{%8,%9},{%0,%1,%2,%3};"
                 : "+f"(c[0]), "+f"(c[1]), "+f"(c[2]), "+f"(c[3])
                 : "r"(a[0]), "r"(a[1]), "r"(a[2]), "r"(a[3]), "r"(b[0]), "r"(b[1]));
}

// fp32 row of 128 -> two bf16 planes in smem, rows of 256B, XOR-16B swizzle
__device__ __forceinline__ void w_row_sts(char* sm, uint32_t oh, uint32_t ol,
                                          const float* __restrict__ src,
                                          int nrows, int tid) {
    for (int i = 0; i < nrows * 32; i += 256) {
        int idx = (tid + i) * 4;
        int m = idx >> 7, k = idx & 127;
        float4 w = *(const float4*)(src + m * 128 + k);
        uint32_t h0, l0, h1, l1;
        bf16_split2(w.x, w.y, h0, l0);
        bf16_split2(w.z, w.w, h1, l1);
        uint32_t byte = (uint32_t)(m * 256) + (((uint32_t)(k * 2)) ^ (((uint32_t)m & 7) << 4));
        *(uint2*)(sm + oh + byte) = make_uint2(h0, h1);
        *(uint2*)(sm + ol + byte) = make_uint2(l0, l1);
    }
}

// 128x64 fp32 tile (row stride NW) -> bf16 planes, rows of 128B, XOR-16B swizzle
__device__ __forceinline__ void x_tile_sts(char* sm, uint32_t oh, uint32_t ol,
                                           const float* __restrict__ xb, int tid) {
    #pragma unroll
    for (int it = 0; it < 8; it++) {
        int idx = tid * 4 + it * 1024;
        int k = idx >> 6, n = idx & 63;
        float4 v = *(const float4*)(xb + (size_t)k * NW + n);
        uint32_t h0, l0, h1, l1;
        bf16_split2(v.x, v.y, h0, l0);
        bf16_split2(v.z, v.w, h1, l1);
        uint32_t byte = (uint32_t)(k * 128) + (((uint32_t)(n * 2)) ^ (((uint32_t)k & 7) << 4));
        *(uint2*)(sm + oh + byte) = make_uint2(h0, h1);
        *(uint2*)(sm + ol + byte) = make_uint2(l0, l1);
    }
}

// ---------------------------------------------------------------------------
__global__ void k_zero() {
    int i = blockIdx.x * blockDim.x + threadIdx.x;
    if (i < NB * 4096) g_S[i] = 0.0f;
    else g_Z[i - NB * 4096] = 0.0f;
}

// ---------------------------------------------------------------------------
// kv = W_kv @ x (HMMA bf16x3); ek/v -> bf16 planes; S/Z in regs, S via tensor
// MMA with NON-TRANS B fragments (v stored [e][n] == [n-major][k] for the MMA).
// smem: Whi 0, Wlo 64K, xhi 128K, xlo 144K, ekhi 160K, eklo 176K,
//       vhi 192K, vlo 208K  (total 224K, disjoint regions)
#define O_XHI 131072u
#define O_XLO 147456u
#define O_EKH 163840u
#define O_EKL 180224u
#define O_VH  196608u
#define O_VL  212992u

__global__ void __launch_bounds__(256, 1)
k_kvctx(const float* __restrict__ x, const float* __restrict__ Wqkv) {
    extern __shared__ char sm[];
    const uint32_t smb = smem_u32(sm);
    const int tid = threadIdx.x, wid = tid >> 5, lane = tid & 31;
    const int mbase = wid * 32;
    const int h = wid >> 1, mh = wid & 1;

    w_row_sts(sm, 0u, 65536u, Wqkv + 128 * 128, 256, tid);

    int per = (NTILES + GRID_SM - 1) / GRID_SM;   // 27
    int lo = blockIdx.x * per, hi = min(NTILES, lo + per);

    float CS[4][4];
    float zacc[4];
    int curb = -1;

    float4 px[8];
    if (lo < hi) {
        const float* xb = x + (size_t)(lo >> 8) * NCH * NW + (size_t)(lo & 255) * 64;
        #pragma unroll
        for (int it = 0; it < 8; it++) {
            int idx = tid * 4 + it * 1024;
            px[it] = *(const float4*)(xb + (size_t)(idx >> 6) * NW + (idx & 63));
        }
    }

    for (int tile = lo; tile < hi; tile++) {
        int b = tile >> 8;
        if (b != curb) {
            if (curb >= 0) {   // flush previous batch
                float* gS = g_S + curb * 4096 + h * 1024;
                int d0 = mh * 16 + (lane >> 2);
                #pragma unroll
                for (int nt = 0; nt < 4; nt++) {
                    int e = nt * 8 + 2 * (lane & 3);
                    atomicAdd(gS + d0 * 32 + e,           CS[nt][0]);
                    atomicAdd(gS + d0 * 32 + e + 1,       CS[nt][1]);
                    atomicAdd(gS + (d0 + 8) * 32 + e,     CS[nt][2]);
                    atomicAdd(gS + (d0 + 8) * 32 + e + 1, CS[nt][3]);
                }
                if (wid < 4 && (lane & 3) == 0) {
                    #pragma unroll
                    for (int mt = 0; mt < 2; mt++) {
                        atomicAdd(g_Z + curb * 128 + mbase + mt * 16 + (lane >> 2),     zacc[mt * 2]);
                        atomicAdd(g_Z + curb * 128 + mbase + mt * 16 + (lane >> 2) + 8, zacc[mt * 2 + 1]);
                    }
                }
            }
            #pragma unroll
            for (int nt = 0; nt < 4; nt++)
                #pragma unroll
                for (int q = 0; q < 4; q++) CS[nt][q] = 0.0f;
            zacc[0] = zacc[1] = zacc[2] = zacc[3] = 0.0f;
            curb = b;
        }

        // STS x from prefetched regs (x region disjoint from ek/v -> safe here)
        #pragma unroll
        for (int it = 0; it < 8; it++) {
            int idx = tid * 4 + it * 1024;
            int k = idx >> 6, n = idx & 63;
            uint32_t h0, l0, h1, l1;
            bf16_split2(px[it].x, px[it].y, h0, l0);
            bf16_split2(px[it].z, px[it].w, h1, l1);
            uint32_t byte = (uint32_t)(k * 128) + (((uint32_t)(n * 2)) ^ (((uint32_t)k & 7) << 4));
            *(uint2*)(sm + O_XHI + byte) = make_uint2(h0, h1);
            *(uint2*)(sm + O_XLO + byte) = make_uint2(l0, l1);
        }
        if (tile + 1 < hi) {
            int nt2 = tile + 1;
            const float* xb = x + (size_t)(nt2 >> 8) * NCH * NW + (size_t)(nt2 & 255) * 64;
            #pragma unroll
            for (int it = 0; it < 8; it++) {
                int idx = tid * 4 + it * 1024;
                px[it] = *(const float4*)(xb + (size_t)(idx >> 6) * NW + (idx & 63));
            }
        }
        __syncthreads();   // sync A: x staged; prior S-GEMM reads of ek/v complete

        // main GEMM: kv(256x64) = W_kv @ x, bf16x3
        float C[2][8][4];
        #pragma unroll
        for (int i = 0; i < 2; i++)
            #pragma unroll
            for (int j = 0; j < 8; j++)
                #pragma unroll
                for (int q = 0; q < 4; q++) C[i][j][q] = 0.0f;

        #pragma unroll
        for (int pass = 0; pass < 3; pass++) {
            uint32_t Ab = smb + (pass == 2 ? 65536u : 0u);
            uint32_t Bb = smb + (pass == 1 ? O_XLO : O_XHI);
            #pragma unroll
            for (int ks = 0; ks < 8; ks++) {
                int k0 = ks * 16;
                uint32_t a[2][4], bfr[4][4];
                #pragma unroll
                for (int mt = 0; mt < 2; mt++) {
                    int row = mbase + mt * 16 + (lane & 15);
                    uint32_t kb = (uint32_t)((k0 + ((lane >> 4) << 3)) * 2);
                    ldsm_x4(a[mt], Ab + (uint32_t)(row * 256) + (kb ^ (((uint32_t)row & 7) << 4)));
                }
                #pragma unroll
                for (int t2 = 0; t2 < 4; t2++) {
                    int krow = k0 + (lane & 15);
                    uint32_t nb = (uint32_t)((t2 * 16 + ((lane >> 4) << 3)) * 2);
                    ldsm_x4t(bfr[t2], Bb + (uint32_t)(krow * 128) + (nb ^ (((uint32_t)krow & 7) << 4)));
                }
                #pragma unroll
                for (int mt = 0; mt < 2; mt++)
                    #pragma unroll
                    for (int t2 = 0; t2 < 4; t2++) {
                        mma16816(C[mt][t2 * 2],     a[mt], &bfr[t2][0]);
                        mma16816(C[mt][t2 * 2 + 1], a[mt], &bfr[t2][2]);
                    }
            }
        }

        // epilogue: ek/v regions are disjoint from x/W; prior readers synced at A
        if (wid < 4) {
            float zp[4] = {0.0f, 0.0f, 0.0f, 0.0f};
            #pragma unroll
            for (int mt = 0; mt < 2; mt++) {
                int r0 = mbase + mt * 16 + (lane >> 2);
                int r1 = r0 + 8;
                #pragma unroll
                for (int nt = 0; nt < 8; nt++) {
                    int cc = nt * 8 + 2 * (lane & 3);
                    float e0 = __expf(C[mt][nt][0]);
                    float e1 = __expf(C[mt][nt][1]);
                    float e2 = __expf(C[mt][nt][2]);
                    float e3 = __expf(C[mt][nt][3]);
                    zp[mt * 2]     += e0 + e1;
                    zp[mt * 2 + 1] += e2 + e3;
                    uint32_t hh, ll;
                    bf16_split2(e0, e1, hh, ll);
                    uint32_t byte = (uint32_t)(r0 * 128)
                                  + (((uint32_t)(cc * 2)) ^ (((uint32_t)r0 & 7) << 4));
                    *(uint32_t*)(sm + O_EKH + byte) = hh;
                    *(uint32_t*)(sm + O_EKL + byte) = ll;
                    bf16_split2(e2, e3, hh, ll);
                    byte = (uint32_t)(r1 * 128)
                         + (((uint32_t)(cc * 2)) ^ (((uint32_t)r1 & 7) << 4));
                    *(uint32_t*)(sm + O_EKH + byte) = hh;
                    *(uint32_t*)(sm + O_EKL + byte) = ll;
                }
            }
            #pragma unroll
            for (int i = 0; i < 4; i++) {
                zp[i] += __shfl_xor_sync(0xFFFFFFFFu, zp[i], 1);
                zp[i] += __shfl_xor_sync(0xFFFFFFFFu, zp[i], 2);
                zacc[i] += zp[i];
            }
        } else {
            #pragma unroll
            for (int mt = 0; mt < 2; mt++) {
                int r0 = mbase - 128 + mt * 16 + (lane >> 2);
                int r1 = r0 + 8;
                #pragma unroll
                for (int nt = 0; nt < 8; nt++) {
                    int cc = nt * 8 + 2 * (lane & 3);
                    uint32_t hh, ll;
                    bf16_split2(C[mt][nt][0], C[mt][nt][1], hh, ll);
                    uint32_t byte = (uint32_t)(r0 * 128)
                                  + (((uint32_t)(cc * 2)) ^ (((uint32_t)r0 & 7) << 4));
                    *(uint32_t*)(sm + O_VH + byte) = hh;
                    *(uint32_t*)(sm + O_VL + byte) = ll;
                    bf16_split2(C[mt][nt][2], C[mt][nt][3], hh, ll);
                    byte = (uint32_t)(r1 * 128)
                         + (((uint32_t)(cc * 2)) ^ (((uint32_t)r1 & 7) << 4));
                    *(uint32_t*)(sm + O_VH + byte) = hh;
                    *(uint32_t*)(sm + O_VL + byte) = ll;
                }
            }
        }
        __syncthreads();   // sync B: ek/v complete

        // S-GEMM: per head, S[d][e] += sum_n ek[d,n]*v[e,n]; bf16x3; reg accum.
        // B fragments: NON-TRANS ldsm on v rows ([e][n] is already col-major B).
        {
            int arow = h * 32 + mh * 16 + (lane & 15);
            uint32_t acol = (uint32_t)((lane >> 4) << 4);          // A k-half, 16B
            int erow_in = ((lane >> 4) << 3) + (lane & 7);          // e row within 16
            uint32_t bsel = (uint32_t)(((lane >> 3) & 1) << 4);     // B k-half, 16B
            #pragma unroll
            for (int pass = 0; pass < 3; pass++) {
                uint32_t Ab = smb + (pass == 2 ? O_EKL : O_EKH);
                uint32_t Bb = smb + (pass == 1 ? O_VL : O_VH);
                #pragma unroll
                for (int ks = 0; ks < 4; ks++) {
                    uint32_t kb = (uint32_t)(ks * 32);
                    uint32_t a[4];
                    uint32_t ka = kb + acol;
                    ldsm_x4(a, Ab + (uint32_t)(arow * 128) + (ka ^ (((uint32_t)arow & 7) << 4)));
                    #pragma unroll
                    for (int et = 0; et < 2; et++) {
                        int er = h * 32 + et * 16 + erow_in;
                        uint32_t kc = kb + bsel;
                        uint32_t bfr[4];
                        ldsm_x4(bfr, Bb + (uint32_t)(er * 128) + (kc ^ (((uint32_t)er & 7) << 4)));
                        mma16816(CS[et * 2],     a, &bfr[0]);
                        mma16816(CS[et * 2 + 1], a, &bfr[2]);
                    }
                }
            }
        }
    }

    // final flush
    if (curb >= 0) {
        float* gS = g_S + curb * 4096 + h * 1024;
        int d0 = mh * 16 + (lane >> 2);
        #pragma unroll
        for (int nt = 0; nt < 4; nt++) {
            int e = nt * 8 + 2 * (lane & 3);
            atomicAdd(gS + d0 * 32 + e,           CS[nt][0]);
            atomicAdd(gS + d0 * 32 + e + 1,       CS[nt][1]);
            atomicAdd(gS + (d0 + 8) * 32 + e,     CS[nt][2]);
            atomicAdd(gS + (d0 + 8) * 32 + e + 1, CS[nt][3]);
        }
        if (wid < 4 && (lane & 3) == 0) {
            #pragma unroll
            for (int mt = 0; mt < 2; mt++) {
                atomicAdd(g_Z + curb * 128 + mbase + mt * 16 + (lane >> 2),     zacc[mt * 2]);
                atomicAdd(g_Z + curb * 128 + mbase + mt * 16 + (lane >> 2) + 8, zacc[mt * 2 + 1]);
            }
        }
    }
}

// ---------------------------------------------------------------------------
__global__ void k_mbuild(const float* __restrict__ Wout) {
    __shared__ float sCtx[4096];
    __shared__ float sWo[16 * 128];
    int b = blockIdx.y, o0 = blockIdx.x * 16;
    int tid = threadIdx.x;
    for (int idx = tid * 4; idx < 4096; idx += 1024) {
        float4 sv = *(const float4*)(g_S + b * 4096 + idx);
        float z = g_Z[b * 128 + (idx >> 5)];
        float r = 1.0f / (z * (float)NW);
        sv.x *= r; sv.y *= r; sv.z *= r; sv.w *= r;
        *(float4*)(sCtx + idx) = sv;
    }
    for (int idx = tid * 4; idx < 2048; idx += 1024)
        *(float4*)(sWo + idx) = *(const float4*)(Wout + (size_t)o0 * 128 + idx);
    __syncthreads();
    for (int idx = tid; idx < 2048; idx += 256) {
        int orr = idx >> 7, hd = idx & 127;
        int hh = hd >> 5, d = hd & 31;
        const float* wrow = sWo + orr * 128 + hh * 32;
        const float* crow = sCtx + hh * 1024 + d * 32;
        float sum = 0.0f;
        #pragma unroll
        for (int e4 = 0; e4 < 8; e4++) {
            float4 w4 = *(const float4*)(wrow + e4 * 4);
            float4 c4 = *(const float4*)(crow + e4 * 4);
            sum += w4.x * c4.x + w4.y * c4.y + w4.z * c4.z + w4.w * c4.w;
        }
        g_M[b * 16384 + (o0 + orr) * 128 + hd] = SCALE_F * sum;
    }
}

// ---------------------------------------------------------------------------
// q = W_q @ x (HMMA); head-softmax in frags; y = M_b @ qsm (HMMA); bias+LN
__global__ void __launch_bounds__(256, 1)
k_qout(const float* __restrict__ x, const float* __restrict__ Wqkv,
       const float* __restrict__ b_out, const float* __restrict__ gamma,
       const float* __restrict__ beta, float* __restrict__ out) {
    extern __shared__ char sm[];
    __shared__ float sBias[128], sGamma[128], sBeta[128], sStat[128];
    __shared__ float sPS[256], sPQ[256];
    const uint32_t smb = smem_u32(sm);
    float* sY = (float*)(sm + 163840);
    const int tid = threadIdx.x, wid = tid >> 5, lane = tid & 31;
    const int mbase = (wid >> 1) * 32;
    const int nbase = (wid & 1) * 32;

    w_row_sts(sm, 0u, 32768u, Wqkv, 128, tid);
    if (tid < 128) {
        sBias[tid] = b_out[tid]; sGamma[tid] = gamma[tid]; sBeta[tid] = beta[tid];
    }

    int per = (NTILES + GRID_SM - 1) / GRID_SM;
    int lo = blockIdx.x * per, hi = min(NTILES, lo + per);
    int curb = -1;

    for (int tile = lo; tile < hi; tile++) {
        int b = tile >> 8, n0 = (tile & 255) * 64;
        if (b != curb) {
            __syncthreads();
            w_row_sts(sm, 65536u, 98304u, g_M + (size_t)b * 16384, 128, tid);
            curb = b;
        }
        __syncthreads();
        x_tile_sts(sm, 131072u, 147456u, x + (size_t)b * NCH * NW + n0, tid);
        __syncthreads();

        float C[2][4][4];
        #define DO_GEMM(ABASE0)                                                          \
        do {                                                                             \
            _Pragma("unroll")                                                            \
            for (int i = 0; i < 2; i++)                                                  \
                _Pragma("unroll")                                                        \
                for (int j = 0; j < 4; j++)                                              \
                    _Pragma("unroll")                                                    \
                    for (int q = 0; q < 4; q++) C[i][j][q] = 0.0f;                       \
            _Pragma("unroll")                                                            \
            for (int pass = 0; pass < 3; pass++) {                                       \
                uint32_t Ab = smb + (ABASE0) + (pass == 2 ? 32768u : 0u);                \
                uint32_t Bb = smb + 131072u + (pass == 1 ? 16384u : 0u);                 \
                _Pragma("unroll")                                                        \
                for (int ks = 0; ks < 8; ks++) {                                         \
                    int k0 = ks * 16;                                                    \
                    uint32_t a[2][4], bfr[2][4];                                         \
                    _Pragma("unroll")                                                    \
                    for (int mt = 0; mt < 2; mt++) {                                     \
                        int row = mbase + mt * 16 + (lane & 15);                         \
                        uint32_t kb = (uint32_t)((k0 + ((lane >> 4) << 3)) * 2);         \
                        ldsm_x4(a[mt], Ab + (uint32_t)(row * 256)                        \
                                + (kb ^ (((uint32_t)row & 7) << 4)));                    \
                    }                                                                    \
                    _Pragma("unroll")                                                    \
                    for (int t2 = 0; t2 < 2; t2++) {                                     \
                        int krow = k0 + (lane & 15);                                     \
                        uint32_t nb = (uint32_t)((nbase * 2)                             \
                                + (t2 * 16 + ((lane >> 4) << 3)) * 2);                   \
                        ldsm_x4t(bfr[t2], Bb + (uint32_t)(krow * 128)                    \
                                + (nb ^ (((uint32_t)krow & 7) << 4)));                   \
                    }                                                                    \
                    _Pragma("unroll")                                                    \
                    for (int mt = 0; mt < 2; mt++)                                       \
                        _Pragma("unroll")                                                \
                        for (int t2 = 0; t2 < 2; t2++) {                                 \
                            mma16816(C[mt][t2 * 2],     a[mt], &bfr[t2][0]);             \
                            mma16816(C[mt][t2 * 2 + 1], a[mt], &bfr[t2][2]);             \
                        }                                                                \
                }                                                                        \
            }                                                                            \
        } while (0)

        DO_GEMM(0u);
        __syncthreads();

        {   // softmax over head-dim
            #pragma unroll
            for (int nt = 0; nt < 4; nt++) {
                float p0 = 0.0f, p1 = 0.0f;
                #pragma unroll
                for (int mt = 0; mt < 2; mt++) {
                    #pragma unroll
                    for (int q = 0; q < 4; q++) C[mt][nt][q] = __expf(C[mt][nt][q]);
                    p0 += C[mt][nt][0] + C[mt][nt][2];
                    p1 += C[mt][nt][1] + C[mt][nt][3];
                }
                p0 += __shfl_xor_sync(0xFFFFFFFFu, p0, 4);
                p0 += __shfl_xor_sync(0xFFFFFFFFu, p0, 8);
                p0 += __shfl_xor_sync(0xFFFFFFFFu, p0, 16);
                p1 += __shfl_xor_sync(0xFFFFFFFFu, p1, 4);
                p1 += __shfl_xor_sync(0xFFFFFFFFu, p1, 8);
                p1 += __shfl_xor_sync(0xFFFFFFFFu, p1, 16);
                float r0 = __fdividef(1.0f, p0), r1 = __fdividef(1.0f, p1);
                #pragma unroll
                for (int mt = 0; mt < 2; mt++) {
                    C[mt][nt][0] *= r0; C[mt][nt][2] *= r0;
                    C[mt][nt][1] *= r1; C[mt][nt][3] *= r1;
                }
            }
            #pragma unroll
            for (int mt = 0; mt < 2; mt++)
                #pragma unroll
                for (int nt = 0; nt < 4; nt++) {
                    int r0 = mbase + mt * 16 + (lane >> 2);
                    int cc = nbase + nt * 8 + 2 * (lane & 3);
                    uint32_t hh, ll;
                    bf16_split2(C[mt][nt][0], C[mt][nt][1], hh, ll);
                    uint32_t byte = (uint32_t)(r0 * 128)
                                  + (((uint32_t)(cc * 2)) ^ (((uint32_t)r0 & 7) << 4));
                    *(uint32_t*)(sm + 131072 + byte) = hh;
                    *(uint32_t*)(sm + 147456 + byte) = ll;
                    int r1 = r0 + 8;
                    bf16_split2(C[mt][nt][2], C[mt][nt][3], hh, ll);
                    byte = (uint32_t)(r1 * 128)
                         + (((uint32_t)(cc * 2)) ^ (((uint32_t)r1 & 7) << 4));
                    *(uint32_t*)(sm + 131072 + byte) = hh;
                    *(uint32_t*)(sm + 147456 + byte) = ll;
                }
        }
        __syncthreads();

        DO_GEMM(65536u);
        #undef DO_GEMM

        {
            #pragma unroll
            for (int mt = 0; mt < 2; mt++)
                #pragma unroll
                for (int nt = 0; nt < 4; nt++) {
                    int r0 = mbase + mt * 16 + (lane >> 2);
                    int cc = nbase + nt * 8 + 2 * (lane & 3);
                    float b0 = sBias[r0], b1 = sBias[r0 + 8];
                    *(float2*)(sY + r0 * 68 + cc) =
                        make_float2(C[mt][nt][0] + b0, C[mt][nt][1] + b0);
                    *(float2*)(sY + (r0 + 8) * 68 + cc) =
                        make_float2(C[mt][nt][2] + b1, C[mt][nt][3] + b1);
                }
        }
        __syncthreads();
        {   // LN stats: 256-thread partials over row quarters
            int c = tid & 63, qr = tid >> 6;
            float s = 0.0f, sq = 0.0f;
            #pragma unroll 8
            for (int rr = qr * 32; rr < qr * 32 + 32; rr++) {
                float v = sY[rr * 68 + c];
                s += v; sq += v * v;
            }
            sPS[qr * 64 + c] = s;
            sPQ[qr * 64 + c] = sq;
        }
        __syncthreads();
        if (tid < 64) {
            float s  = sPS[tid] + sPS[64 + tid] + sPS[128 + tid] + sPS[192 + tid];
            float sq = sPQ[tid] + sPQ[64 + tid] + sPQ[128 + tid] + sPQ[192 + tid];
            float mean = s * (1.0f / 128.0f);
            float var = sq * (1.0f / 128.0f) - mean * mean;
            sStat[tid * 2] = mean;
            sStat[tid * 2 + 1] = rsqrtf(var + LN_EPS);
        }
        __syncthreads();
        float* ob = out + (size_t)b * NCH * NW + n0;
        for (int idx = tid * 4; idx < 8192; idx += 1024) {
            int rr = idx >> 6, cc = idx & 63;
            float4 v = *(const float4*)(sY + rr * 68 + cc);
            float g = sGamma[rr], be = sBeta[rr];
            v.x = (v.x - sStat[2 * cc])       * sStat[2 * cc + 1]       * g + be;
            v.y = (v.y - sStat[2 * (cc + 1)]) * sStat[2 * (cc + 1) + 1] * g + be;
            v.z = (v.z - sStat[2 * (cc + 2)]) * sStat[2 * (cc + 2) + 1] * g + be;
            v.w = (v.w - sStat[2 * (cc + 3)]) * sStat[2 * (cc + 3) + 1] * g + be;
            *(float4*)(ob + (size_t)rr * NW + cc) = v;
        }
    }
}

// ---------------------------------------------------------------------------
extern "C" void kernel_launch(void* const* d_in, const int* in_sizes, int n_in,
                              void* d_out, int out_size) {
    const float* x    = (const float*)d_in[0];
    const float* Wqkv = (const float*)d_in[1];
    const float* Wout = (const float*)d_in[2];
    const float* bo   = (const float*)d_in[3];
    const float* gm   = (const float*)d_in[4];
    const float* bt   = (const float*)d_in[5];
    float* out = (float*)d_out;

    const int SMEM_A = 229376;
    const int SMEM_C = 198656;
    cudaFuncSetAttribute(k_kvctx, cudaFuncAttributeMaxDynamicSharedMemorySize, SMEM_A);
    cudaFuncSetAttribute(k_qout,  cudaFuncAttributeMaxDynamicSharedMemorySize, SMEM_C);

    k_zero<<<66, 1024>>>();
    k_kvctx<<<GRID_SM, 256, SMEM_A>>>(x, Wqkv);
    k_mbuild<<<dim3(8, 16), 256>>>(Wout);
    k_qout<<<GRID_SM, 256, SMEM_C>>>(x, Wqkv, bo, gm, bt, out);
}

// round 10
// speedup vs baseline: 2.3658x; 1.0349x over previous
#include <cuda_runtime.h>
#include <cstdint>

#define NB 16
#define NCH 128
#define NW 16384
#define NTILES 4096
#define GRID_SM 152
#define SCALE_F 0.17677669529663687f
#define LN_EPS 1e-5f

__device__ float g_S[NB * 4096];
__device__ float g_Z[NB * 128];
__device__ float g_M[NB * 128 * 128];

__device__ __forceinline__ uint32_t smem_u32(const void* p) {
    uint32_t a;
    asm("{ .reg .u64 t; cvta.to.shared.u64 t, %1; cvt.u32.u64 %0, t; }" : "=r"(a) : "l"(p));
    return a;
}
__device__ __forceinline__ void bf16_split2(float a, float b, uint32_t& h, uint32_t& l) {
    asm("cvt.rn.bf16x2.f32 %0, %1, %2;" : "=r"(h) : "f"(b), "f"(a));
    float ra = a - __uint_as_float(h << 16);
    float rb = b - __uint_as_float(h & 0xFFFF0000u);
    asm("cvt.rn.bf16x2.f32 %0, %1, %2;" : "=r"(l) : "f"(rb), "f"(ra));
}
__device__ __forceinline__ void ldsm_x4(uint32_t* a, uint32_t addr) {
    asm volatile("ldmatrix.sync.aligned.m8n8.x4.shared.b16 {%0,%1,%2,%3}, [%4];"
                 : "=r"(a[0]), "=r"(a[1]), "=r"(a[2]), "=r"(a[3]) : "r"(addr));
}
__device__ __forceinline__ void ldsm_x4t(uint32_t* a, uint32_t addr) {
    asm volatile("ldmatrix.sync.aligned.m8n8.x4.trans.shared.b16 {%0,%1,%2,%3}, [%4];"
                 : "=r"(a[0]), "=r"(a[1]), "=r"(a[2]), "=r"(a[3]) : "r"(addr));
}
__device__ __forceinline__ void mma16816(float* c, const uint32_t* a, const uint32_t* b) {
    asm volatile("mma.sync.aligned.m16n8k16.row.col.f32.bf16.bf16.f32 "
                 "{%0,%1,%2,%3},{%4,%5,%6,%7},{%8,%9},{%0,%1,%2,%3};"
                 : "+f"(c[0]), "+f"(c[1]), "+f"(c[2]), "+f"(c[3])
                 : "r"(a[0]), "r"(a[1]), "r"(a[2]), "r"(a[3]), "r"(b[0]), "r"(b[1]));
}
__device__ __forceinline__ void cp_async16(uint32_t dst, const void* src) {
    asm volatile("cp.async.cg.shared.global [%0], [%1], 16;" :: "r"(dst), "l"(src));
}

// fp32 rows of 128 -> two bf16 planes in smem, rows of 256B, XOR-16B swizzle
__device__ __forceinline__ void w_row_sts(char* sm, uint32_t oh, uint32_t ol,
                                          const float* __restrict__ src,
                                          int nrows, int tid, int nthreads) {
    for (int idx = tid * 4; idx < nrows * 128; idx += nthreads * 4) {
        int m = idx >> 7, k = idx & 127;
        float4 w = *(const float4*)(src + m * 128 + k);
        uint32_t h0, l0, h1, l1;
        bf16_split2(w.x, w.y, h0, l0);
        bf16_split2(w.z, w.w, h1, l1);
        uint32_t byte = (uint32_t)(m * 256) + (((uint32_t)(k * 2)) ^ (((uint32_t)m & 7) << 4));
        *(uint2*)(sm + oh + byte) = make_uint2(h0, h1);
        *(uint2*)(sm + ol + byte) = make_uint2(l0, l1);
    }
}

// ---------------------------------------------------------------------------
__global__ void k_zero() {
    int i = blockIdx.x * blockDim.x + threadIdx.x;
    if (i < NB * 4096) g_S[i] = 0.0f;
    else g_Z[i - NB * 4096] = 0.0f;
}

// ---------------------------------------------------------------------------
// k_kvctx: UNCHANGED from R8 (passing, rel_err 8.5e-6)
#define O_XHI 131072u
#define O_XLO 147456u
#define O_EKH 163840u
#define O_EKL 180224u
#define O_VH  196608u
#define O_VL  212992u

__global__ void __launch_bounds__(256, 1)
k_kvctx(const float* __restrict__ x, const float* __restrict__ Wqkv) {
    extern __shared__ char sm[];
    const uint32_t smb = smem_u32(sm);
    const int tid = threadIdx.x, wid = tid >> 5, lane = tid & 31;
    const int mbase = wid * 32;
    const int h = wid >> 1, mh = wid & 1;

    w_row_sts(sm, 0u, 65536u, Wqkv + 128 * 128, 256, tid, 256);

    int per = (NTILES + GRID_SM - 1) / GRID_SM;   // 27
    int lo = blockIdx.x * per, hi = min(NTILES, lo + per);

    float CS[4][4];
    float zacc[4];
    int curb = -1;

    float4 px[8];
    if (lo < hi) {
        const float* xb = x + (size_t)(lo >> 8) * NCH * NW + (size_t)(lo & 255) * 64;
        #pragma unroll
        for (int it = 0; it < 8; it++) {
            int idx = tid * 4 + it * 1024;
            px[it] = *(const float4*)(xb + (size_t)(idx >> 6) * NW + (idx & 63));
        }
    }

    for (int tile = lo; tile < hi; tile++) {
        int b = tile >> 8;
        if (b != curb) {
            if (curb >= 0) {
                float* gS = g_S + curb * 4096 + h * 1024;
                int d0 = mh * 16 + (lane >> 2);
                #pragma unroll
                for (int nt = 0; nt < 4; nt++) {
                    int e = nt * 8 + 2 * (lane & 3);
                    atomicAdd(gS + d0 * 32 + e,           CS[nt][0]);
                    atomicAdd(gS + d0 * 32 + e + 1,       CS[nt][1]);
                    atomicAdd(gS + (d0 + 8) * 32 + e,     CS[nt][2]);
                    atomicAdd(gS + (d0 + 8) * 32 + e + 1, CS[nt][3]);
                }
                if (wid < 4 && (lane & 3) == 0) {
                    #pragma unroll
                    for (int mt = 0; mt < 2; mt++) {
                        atomicAdd(g_Z + curb * 128 + mbase + mt * 16 + (lane >> 2),     zacc[mt * 2]);
                        atomicAdd(g_Z + curb * 128 + mbase + mt * 16 + (lane >> 2) + 8, zacc[mt * 2 + 1]);
                    }
                }
            }
            #pragma unroll
            for (int nt = 0; nt < 4; nt++)
                #pragma unroll
                for (int q = 0; q < 4; q++) CS[nt][q] = 0.0f;
            zacc[0] = zacc[1] = zacc[2] = zacc[3] = 0.0f;
            curb = b;
        }

        #pragma unroll
        for (int it = 0; it < 8; it++) {
            int idx = tid * 4 + it * 1024;
            int k = idx >> 6, n = idx & 63;
            uint32_t h0, l0, h1, l1;
            bf16_split2(px[it].x, px[it].y, h0, l0);
            bf16_split2(px[it].z, px[it].w, h1, l1);
            uint32_t byte = (uint32_t)(k * 128) + (((uint32_t)(n * 2)) ^ (((uint32_t)k & 7) << 4));
            *(uint2*)(sm + O_XHI + byte) = make_uint2(h0, h1);
            *(uint2*)(sm + O_XLO + byte) = make_uint2(l0, l1);
        }
        if (tile + 1 < hi) {
            int nt2 = tile + 1;
            const float* xb = x + (size_t)(nt2 >> 8) * NCH * NW + (size_t)(nt2 & 255) * 64;
            #pragma unroll
            for (int it = 0; it < 8; it++) {
                int idx = tid * 4 + it * 1024;
                px[it] = *(const float4*)(xb + (size_t)(idx >> 6) * NW + (idx & 63));
            }
        }
        __syncthreads();

        float C[2][8][4];
        #pragma unroll
        for (int i = 0; i < 2; i++)
            #pragma unroll
            for (int j = 0; j < 8; j++)
                #pragma unroll
                for (int q = 0; q < 4; q++) C[i][j][q] = 0.0f;

        #pragma unroll
        for (int pass = 0; pass < 3; pass++) {
            uint32_t Ab = smb + (pass == 2 ? 65536u : 0u);
            uint32_t Bb = smb + (pass == 1 ? O_XLO : O_XHI);
            #pragma unroll
            for (int ks = 0; ks < 8; ks++) {
                int k0 = ks * 16;
                uint32_t a[2][4], bfr[4][4];
                #pragma unroll
                for (int mt = 0; mt < 2; mt++) {
                    int row = mbase + mt * 16 + (lane & 15);
                    uint32_t kb = (uint32_t)((k0 + ((lane >> 4) << 3)) * 2);
                    ldsm_x4(a[mt], Ab + (uint32_t)(row * 256) + (kb ^ (((uint32_t)row & 7) << 4)));
                }
                #pragma unroll
                for (int t2 = 0; t2 < 4; t2++) {
                    int krow = k0 + (lane & 15);
                    uint32_t nb = (uint32_t)((t2 * 16 + ((lane >> 4) << 3)) * 2);
                    ldsm_x4t(bfr[t2], Bb + (uint32_t)(krow * 128) + (nb ^ (((uint32_t)krow & 7) << 4)));
                }
                #pragma unroll
                for (int mt = 0; mt < 2; mt++)
                    #pragma unroll
                    for (int t2 = 0; t2 < 4; t2++) {
                        mma16816(C[mt][t2 * 2],     a[mt], &bfr[t2][0]);
                        mma16816(C[mt][t2 * 2 + 1], a[mt], &bfr[t2][2]);
                    }
            }
        }

        if (wid < 4) {
            float zp[4] = {0.0f, 0.0f, 0.0f, 0.0f};
            #pragma unroll
            for (int mt = 0; mt < 2; mt++) {
                int r0 = mbase + mt * 16 + (lane >> 2);
                int r1 = r0 + 8;
                #pragma unroll
                for (int nt = 0; nt < 8; nt++) {
                    int cc = nt * 8 + 2 * (lane & 3);
                    float e0 = __expf(C[mt][nt][0]);
                    float e1 = __expf(C[mt][nt][1]);
                    float e2 = __expf(C[mt][nt][2]);
                    float e3 = __expf(C[mt][nt][3]);
                    zp[mt * 2]     += e0 + e1;
                    zp[mt * 2 + 1] += e2 + e3;
                    uint32_t hh, ll;
                    bf16_split2(e0, e1, hh, ll);
                    uint32_t byte = (uint32_t)(r0 * 128)
                                  + (((uint32_t)(cc * 2)) ^ (((uint32_t)r0 & 7) << 4));
                    *(uint32_t*)(sm + O_EKH + byte) = hh;
                    *(uint32_t*)(sm + O_EKL + byte) = ll;
                    bf16_split2(e2, e3, hh, ll);
                    byte = (uint32_t)(r1 * 128)
                         + (((uint32_t)(cc * 2)) ^ (((uint32_t)r1 & 7) << 4));
                    *(uint32_t*)(sm + O_EKH + byte) = hh;
                    *(uint32_t*)(sm + O_EKL + byte) = ll;
                }
            }
            #pragma unroll
            for (int i = 0; i < 4; i++) {
                zp[i] += __shfl_xor_sync(0xFFFFFFFFu, zp[i], 1);
                zp[i] += __shfl_xor_sync(0xFFFFFFFFu, zp[i], 2);
                zacc[i] += zp[i];
            }
        } else {
            #pragma unroll
            for (int mt = 0; mt < 2; mt++) {
                int r0 = mbase - 128 + mt * 16 + (lane >> 2);
                int r1 = r0 + 8;
                #pragma unroll
                for (int nt = 0; nt < 8; nt++) {
                    int cc = nt * 8 + 2 * (lane & 3);
                    uint32_t hh, ll;
                    bf16_split2(C[mt][nt][0], C[mt][nt][1], hh, ll);
                    uint32_t byte = (uint32_t)(r0 * 128)
                                  + (((uint32_t)(cc * 2)) ^ (((uint32_t)r0 & 7) << 4));
                    *(uint32_t*)(sm + O_VH + byte) = hh;
                    *(uint32_t*)(sm + O_VL + byte) = ll;
                    bf16_split2(C[mt][nt][2], C[mt][nt][3], hh, ll);
                    byte = (uint32_t)(r1 * 128)
                         + (((uint32_t)(cc * 2)) ^ (((uint32_t)r1 & 7) << 4));
                    *(uint32_t*)(sm + O_VH + byte) = hh;
                    *(uint32_t*)(sm + O_VL + byte) = ll;
                }
            }
        }
        __syncthreads();

        {
            int arow = h * 32 + mh * 16 + (lane & 15);
            uint32_t acol = (uint32_t)((lane >> 4) << 4);
            int erow_in = ((lane >> 4) << 3) + (lane & 7);
            uint32_t bsel = (uint32_t)(((lane >> 3) & 1) << 4);
            #pragma unroll
            for (int pass = 0; pass < 3; pass++) {
                uint32_t Ab = smb + (pass == 2 ? O_EKL : O_EKH);
                uint32_t Bb = smb + (pass == 1 ? O_VL : O_VH);
                #pragma unroll
                for (int ks = 0; ks < 4; ks++) {
                    uint32_t kb = (uint32_t)(ks * 32);
                    uint32_t a[4];
                    uint32_t ka = kb + acol;
                    ldsm_x4(a, Ab + (uint32_t)(arow * 128) + (ka ^ (((uint32_t)arow & 7) << 4)));
                    #pragma unroll
                    for (int et = 0; et < 2; et++) {
                        int er = h * 32 + et * 16 + erow_in;
                        uint32_t kc = kb + bsel;
                        uint32_t bfr[4];
                        ldsm_x4(bfr, Bb + (uint32_t)(er * 128) + (kc ^ (((uint32_t)er & 7) << 4)));
                        mma16816(CS[et * 2],     a, &bfr[0]);
                        mma16816(CS[et * 2 + 1], a, &bfr[2]);
                    }
                }
            }
        }
    }

    if (curb >= 0) {
        float* gS = g_S + curb * 4096 + h * 1024;
        int d0 = mh * 16 + (lane >> 2);
        #pragma unroll
        for (int nt = 0; nt < 4; nt++) {
            int e = nt * 8 + 2 * (lane & 3);
            atomicAdd(gS + d0 * 32 + e,           CS[nt][0]);
            atomicAdd(gS + d0 * 32 + e + 1,       CS[nt][1]);
            atomicAdd(gS + (d0 + 8) * 32 + e,     CS[nt][2]);
            atomicAdd(gS + (d0 + 8) * 32 + e + 1, CS[nt][3]);
        }
        if (wid < 4 && (lane & 3) == 0) {
            #pragma unroll
            for (int mt = 0; mt < 2; mt++) {
                atomicAdd(g_Z + curb * 128 + mbase + mt * 16 + (lane >> 2),     zacc[mt * 2]);
                atomicAdd(g_Z + curb * 128 + mbase + mt * 16 + (lane >> 2) + 8, zacc[mt * 2 + 1]);
            }
        }
    }
}

// ---------------------------------------------------------------------------
__global__ void k_mbuild(const float* __restrict__ Wout) {
    __shared__ float sCtx[4096];
    __shared__ float sWo[16 * 128];
    int b = blockIdx.y, o0 = blockIdx.x * 16;
    int tid = threadIdx.x;
    for (int idx = tid * 4; idx < 4096; idx += 1024) {
        float4 sv = *(const float4*)(g_S + b * 4096 + idx);
        float z = g_Z[b * 128 + (idx >> 5)];
        float r = 1.0f / (z * (float)NW);
        sv.x *= r; sv.y *= r; sv.z *= r; sv.w *= r;
        *(float4*)(sCtx + idx) = sv;
    }
    for (int idx = tid * 4; idx < 2048; idx += 1024)
        *(float4*)(sWo + idx) = *(const float4*)(Wout + (size_t)o0 * 128 + idx);
    __syncthreads();
    for (int idx = tid; idx < 2048; idx += 256) {
        int orr = idx >> 7, hd = idx & 127;
        int hh = hd >> 5, d = hd & 31;
        const float* wrow = sWo + orr * 128 + hh * 32;
        const float* crow = sCtx + hh * 1024 + d * 32;
        float sum = 0.0f;
        #pragma unroll
        for (int e4 = 0; e4 < 8; e4++) {
            float4 w4 = *(const float4*)(wrow + e4 * 4);
            float4 c4 = *(const float4*)(crow + e4 * 4);
            sum += w4.x * c4.x + w4.y * c4.y + w4.z * c4.z + w4.w * c4.w;
        }
        g_M[b * 16384 + (o0 + orr) * 128 + hd] = SCALE_F * sum;
    }
}

// ---------------------------------------------------------------------------
// k_qout, 512 threads: q = W_q@x (HMMA); softmax in frags; y = M_b@qsm (HMMA);
// bias+LN from fragments; cp.async staging for next x tile.
// smem: Wq hi 0 / lo 32768; M hi 65536 / lo 98304; x/qsm planes 131072/147456;
//       staging (raw fp32 next tile) @163840 (32768). Total dynamic 196608.
#define Q_STG 163840u

__global__ void __launch_bounds__(512, 1)
k_qout(const float* __restrict__ x, const float* __restrict__ Wqkv,
       const float* __restrict__ b_out, const float* __restrict__ gamma,
       const float* __restrict__ beta, float* __restrict__ out) {
    extern __shared__ char sm[];
    __shared__ float sBias[128], sGamma[128], sBeta[128], sStat[128];
    __shared__ float sPS[256], sPQ[256];
    const uint32_t smb = smem_u32(sm);
    const int tid = threadIdx.x, wid = tid >> 5, lane = tid & 31;
    const int mbase = (wid >> 2) * 32;   // 4 warp-rows of 32
    const int nbase = (wid & 3) * 16;    // 4 warp-cols of 16
    const int wrow = wid >> 2;

    w_row_sts(sm, 0u, 32768u, Wqkv, 128, tid, 512);
    if (tid < 128) {
        sBias[tid] = b_out[tid]; sGamma[tid] = gamma[tid]; sBeta[tid] = beta[tid];
    }

    int per = (NTILES + GRID_SM - 1) / GRID_SM;
    int lo = blockIdx.x * per, hi = min(NTILES, lo + per);
    int curb = -1;

    for (int tile = lo; tile < hi; tile++) {
        int b = tile >> 8, n0 = (tile & 255) * 64;
        if (b != curb) {
            __syncthreads();
            w_row_sts(sm, 65536u, 98304u, g_M + (size_t)b * 16384, 128, tid, 512);
            curb = b;
        }
        __syncthreads();   // prior tile's qsm-plane reads complete before overwrite

        if (tile == lo) {
            // first tile: direct LDG + convert
            const float* xb = x + (size_t)b * NCH * NW + n0;
            #pragma unroll
            for (int it = 0; it < 4; it++) {
                int idx = tid * 4 + it * 2048;
                int k = idx >> 6, n = idx & 63;
                float4 v = *(const float4*)(xb + (size_t)k * NW + n);
                uint32_t h0, l0, h1, l1;
                bf16_split2(v.x, v.y, h0, l0);
                bf16_split2(v.z, v.w, h1, l1);
                uint32_t byte = (uint32_t)(k * 128) + (((uint32_t)(n * 2)) ^ (((uint32_t)k & 7) << 4));
                *(uint2*)(sm + 131072u + byte) = make_uint2(h0, h1);
                *(uint2*)(sm + 147456u + byte) = make_uint2(l0, l1);
            }
        } else {
            asm volatile("cp.async.wait_group 0;" ::: "memory");
            #pragma unroll
            for (int it = 0; it < 4; it++) {
                int idx = tid * 4 + it * 2048;
                int k = idx >> 6, n = idx & 63;
                float4 v = *(const float4*)(sm + Q_STG + (uint32_t)idx * 4u);
                uint32_t h0, l0, h1, l1;
                bf16_split2(v.x, v.y, h0, l0);
                bf16_split2(v.z, v.w, h1, l1);
                uint32_t byte = (uint32_t)(k * 128) + (((uint32_t)(n * 2)) ^ (((uint32_t)k & 7) << 4));
                *(uint2*)(sm + 131072u + byte) = make_uint2(h0, h1);
                *(uint2*)(sm + 147456u + byte) = make_uint2(l0, l1);
            }
        }
        __syncthreads();   // x planes ready; staging reads complete

        if (tile + 1 < hi) {   // prefetch next tile's raw fp32 into staging
            int nt2 = tile + 1;
            const float* xb = x + (size_t)(nt2 >> 8) * NCH * NW + (size_t)(nt2 & 255) * 64;
            #pragma unroll
            for (int it = 0; it < 4; it++) {
                int idx = tid * 4 + it * 2048;
                cp_async16(smb + Q_STG + (uint32_t)idx * 4u,
                           xb + (size_t)(idx >> 6) * NW + (idx & 63));
            }
            asm volatile("cp.async.commit_group;" ::: "memory");
        }

        float C[2][2][4];
        #define DO_GEMM(ABASE0)                                                          \
        do {                                                                             \
            _Pragma("unroll")                                                            \
            for (int i = 0; i < 2; i++)                                                  \
                _Pragma("unroll")                                                        \
                for (int j = 0; j < 2; j++)                                              \
                    _Pragma("unroll")                                                    \
                    for (int q = 0; q < 4; q++) C[i][j][q] = 0.0f;                       \
            _Pragma("unroll")                                                            \
            for (int pass = 0; pass < 3; pass++) {                                       \
                uint32_t Ab = smb + (ABASE0) + (pass == 2 ? 32768u : 0u);                \
                uint32_t Bb = smb + 131072u + (pass == 1 ? 16384u : 0u);                 \
                _Pragma("unroll")                                                        \
                for (int ks = 0; ks < 8; ks++) {                                         \
                    int k0 = ks * 16;                                                    \
                    uint32_t a[2][4], bfr[4];                                            \
                    _Pragma("unroll")                                                    \
                    for (int mt = 0; mt < 2; mt++) {                                     \
                        int row = mbase + mt * 16 + (lane & 15);                         \
                        uint32_t kb = (uint32_t)((k0 + ((lane >> 4) << 3)) * 2);         \
                        ldsm_x4(a[mt], Ab + (uint32_t)(row * 256)                        \
                                + (kb ^ (((uint32_t)row & 7) << 4)));                    \
                    }                                                                    \
                    {                                                                    \
                        int krow = k0 + (lane & 15);                                     \
                        uint32_t nb = (uint32_t)((nbase + ((lane >> 4) << 3)) * 2);      \
                        ldsm_x4t(bfr, Bb + (uint32_t)(krow * 128)                        \
                                + (nb ^ (((uint32_t)krow & 7) << 4)));                   \
                    }                                                                    \
                    _Pragma("unroll")                                                    \
                    for (int mt = 0; mt < 2; mt++) {                                     \
                        mma16816(C[mt][0], a[mt], &bfr[0]);                              \
                        mma16816(C[mt][1], a[mt], &bfr[2]);                              \
                    }                                                                    \
                }                                                                        \
            }                                                                            \
        } while (0)

        DO_GEMM(0u);       // q = W_q @ x
        __syncthreads();   // x-plane reads done before qsm overwrite

        {   // softmax over head-dim (warp rows = one head, 32 rows)
            #pragma unroll
            for (int nt = 0; nt < 2; nt++) {
                float p0 = 0.0f, p1 = 0.0f;
                #pragma unroll
                for (int mt = 0; mt < 2; mt++) {
                    #pragma unroll
                    for (int q = 0; q < 4; q++) C[mt][nt][q] = __expf(C[mt][nt][q]);
                    p0 += C[mt][nt][0] + C[mt][nt][2];
                    p1 += C[mt][nt][1] + C[mt][nt][3];
                }
                p0 += __shfl_xor_sync(0xFFFFFFFFu, p0, 4);
                p0 += __shfl_xor_sync(0xFFFFFFFFu, p0, 8);
                p0 += __shfl_xor_sync(0xFFFFFFFFu, p0, 16);
                p1 += __shfl_xor_sync(0xFFFFFFFFu, p1, 4);
                p1 += __shfl_xor_sync(0xFFFFFFFFu, p1, 8);
                p1 += __shfl_xor_sync(0xFFFFFFFFu, p1, 16);
                float r0 = __fdividef(1.0f, p0), r1 = __fdividef(1.0f, p1);
                #pragma unroll
                for (int mt = 0; mt < 2; mt++) {
                    C[mt][nt][0] *= r0; C[mt][nt][2] *= r0;
                    C[mt][nt][1] *= r1; C[mt][nt][3] *= r1;
                }
            }
            #pragma unroll
            for (int mt = 0; mt < 2; mt++)
                #pragma unroll
                for (int nt = 0; nt < 2; nt++) {
                    int r0 = mbase + mt * 16 + (lane >> 2);
                    int cc = nbase + nt * 8 + 2 * (lane & 3);
                    uint32_t hh, ll;
                    bf16_split2(C[mt][nt][0], C[mt][nt][1], hh, ll);
                    uint32_t byte = (uint32_t)(r0 * 128)
                                  + (((uint32_t)(cc * 2)) ^ (((uint32_t)r0 & 7) << 4));
                    *(uint32_t*)(sm + 131072 + byte) = hh;
                    *(uint32_t*)(sm + 147456 + byte) = ll;
                    int r1 = r0 + 8;
                    bf16_split2(C[mt][nt][2], C[mt][nt][3], hh, ll);
                    byte = (uint32_t)(r1 * 128)
                         + (((uint32_t)(cc * 2)) ^ (((uint32_t)r1 & 7) << 4));
                    *(uint32_t*)(sm + 131072 + byte) = hh;
                    *(uint32_t*)(sm + 147456 + byte) = ll;
                }
        }
        __syncthreads();

        DO_GEMM(65536u);   // y = M_b @ qsm
        #undef DO_GEMM

        {   // bias into fragments + LN partial sums from fragments
            float ps[2][2], pq[2][2];   // [nt][col-parity]
            #pragma unroll
            for (int nt = 0; nt < 2; nt++) { ps[nt][0] = ps[nt][1] = pq[nt][0] = pq[nt][1] = 0.0f; }
            #pragma unroll
            for (int mt = 0; mt < 2; mt++) {
                int r0 = mbase + mt * 16 + (lane >> 2);
                float b0 = sBias[r0], b1 = sBias[r0 + 8];
                #pragma unroll
                for (int nt = 0; nt < 2; nt++) {
                    C[mt][nt][0] += b0; C[mt][nt][1] += b0;
                    C[mt][nt][2] += b1; C[mt][nt][3] += b1;
                    ps[nt][0] += C[mt][nt][0] + C[mt][nt][2];
                    ps[nt][1] += C[mt][nt][1] + C[mt][nt][3];
                    pq[nt][0] += C[mt][nt][0] * C[mt][nt][0] + C[mt][nt][2] * C[mt][nt][2];
                    pq[nt][1] += C[mt][nt][1] * C[mt][nt][1] + C[mt][nt][3] * C[mt][nt][3];
                }
            }
            #pragma unroll
            for (int nt = 0; nt < 2; nt++)
                #pragma unroll
                for (int cp = 0; cp < 2; cp++) {
                    ps[nt][cp] += __shfl_xor_sync(0xFFFFFFFFu, ps[nt][cp], 4);
                    ps[nt][cp] += __shfl_xor_sync(0xFFFFFFFFu, ps[nt][cp], 8);
                    ps[nt][cp] += __shfl_xor_sync(0xFFFFFFFFu, ps[nt][cp], 16);
                    pq[nt][cp] += __shfl_xor_sync(0xFFFFFFFFu, pq[nt][cp], 4);
                    pq[nt][cp] += __shfl_xor_sync(0xFFFFFFFFu, pq[nt][cp], 8);
                    pq[nt][cp] += __shfl_xor_sync(0xFFFFFFFFu, pq[nt][cp], 16);
                }
            if (lane < 4) {
                #pragma unroll
                for (int nt = 0; nt < 2; nt++) {
                    int cc = nbase + nt * 8 + 2 * lane;
                    sPS[wrow * 64 + cc]     = ps[nt][0];
                    sPS[wrow * 64 + cc + 1] = ps[nt][1];
                    sPQ[wrow * 64 + cc]     = pq[nt][0];
                    sPQ[wrow * 64 + cc + 1] = pq[nt][1];
                }
            }
        }
        __syncthreads();
        if (tid < 64) {
            float s  = sPS[tid] + sPS[64 + tid] + sPS[128 + tid] + sPS[192 + tid];
            float sq = sPQ[tid] + sPQ[64 + tid] + sPQ[128 + tid] + sPQ[192 + tid];
            float mean = s * (1.0f / 128.0f);
            float var = sq * (1.0f / 128.0f) - mean * mean;
            sStat[tid * 2] = mean;
            sStat[tid * 2 + 1] = rsqrtf(var + LN_EPS);
        }
        __syncthreads();

        {   // apply LN from fragments, store float2s to global
            float* ob = out + (size_t)b * NCH * NW + n0;
            #pragma unroll
            for (int mt = 0; mt < 2; mt++) {
                int r0 = mbase + mt * 16 + (lane >> 2);
                int r1 = r0 + 8;
                float g0 = sGamma[r0], be0 = sBeta[r0];
                float g1 = sGamma[r1], be1 = sBeta[r1];
                #pragma unroll
                for (int nt = 0; nt < 2; nt++) {
                    int cc = nbase + nt * 8 + 2 * (lane & 3);
                    float m0 = sStat[2 * cc],       rs0 = sStat[2 * cc + 1];
                    float m1 = sStat[2 * (cc + 1)], rs1 = sStat[2 * (cc + 1) + 1];
                    *(float2*)(ob + (size_t)r0 * NW + cc) = make_float2(
                        (C[mt][nt][0] - m0) * rs0 * g0 + be0,
                        (C[mt][nt][1] - m1) * rs1 * g0 + be0);
                    *(float2*)(ob + (size_t)r1 * NW + cc) = make_float2(
                        (C[mt][nt][2] - m0) * rs0 * g1 + be1,
                        (C[mt][nt][3] - m1) * rs1 * g1 + be1);
                }
            }
        }
    }
}

// ---------------------------------------------------------------------------
extern "C" void kernel_launch(void* const* d_in, const int* in_sizes, int n_in,
                              void* d_out, int out_size) {
    const float* x    = (const float*)d_in[0];
    const float* Wqkv = (const float*)d_in[1];
    const float* Wout = (const float*)d_in[2];
    const float* bo   = (const float*)d_in[3];
    const float* gm   = (const float*)d_in[4];
    const float* bt   = (const float*)d_in[5];
    float* out = (float*)d_out;

    const int SMEM_A = 229376;
    const int SMEM_C = 196608;
    cudaFuncSetAttribute(k_kvctx, cudaFuncAttributeMaxDynamicSharedMemorySize, SMEM_A);
    cudaFuncSetAttribute(k_qout,  cudaFuncAttributeMaxDynamicSharedMemorySize, SMEM_C);

    k_zero<<<66, 1024>>>();
    k_kvctx<<<GRID_SM, 256, SMEM_A>>>(x, Wqkv);
    k_mbuild<<<dim3(8, 16), 256>>>(Wout);
    k_qout<<<GRID_SM, 512, SMEM_C>>>(x, Wqkv, bo, gm, bt, out);
}

// round 11
// speedup vs baseline: 3.0541x; 1.2909x over previous
#include <cuda_runtime.h>
#include <cstdint>

#define NB 16
#define NCH 128
#define NW 16384
#define NTILES 4096
#define GRID_SM 152
#define SCALE_F 0.17677669529663687f
#define LN_EPS 1e-5f

__device__ float g_S[NB * 4096];
__device__ float g_Z[NB * 128];
__device__ float g_M[NB * 128 * 128];

__device__ __forceinline__ uint32_t smem_u32(const void* p) {
    uint32_t a;
    asm("{ .reg .u64 t; cvta.to.shared.u64 t, %1; cvt.u32.u64 %0, t; }" : "=r"(a) : "l"(p));
    return a;
}
__device__ __forceinline__ void bf16_split2(float a, float b, uint32_t& h, uint32_t& l) {
    asm("cvt.rn.bf16x2.f32 %0, %1, %2;" : "=r"(h) : "f"(b), "f"(a));
    float ra = a - __uint_as_float(h << 16);
    float rb = b - __uint_as_float(h & 0xFFFF0000u);
    asm("cvt.rn.bf16x2.f32 %0, %1, %2;" : "=r"(l) : "f"(rb), "f"(ra));
}
__device__ __forceinline__ void ldsm_x4(uint32_t* a, uint32_t addr) {
    asm volatile("ldmatrix.sync.aligned.m8n8.x4.shared.b16 {%0,%1,%2,%3}, [%4];"
                 : "=r"(a[0]), "=r"(a[1]), "=r"(a[2]), "=r"(a[3]) : "r"(addr));
}
__device__ __forceinline__ void ldsm_x4t(uint32_t* a, uint32_t addr) {
    asm volatile("ldmatrix.sync.aligned.m8n8.x4.trans.shared.b16 {%0,%1,%2,%3}, [%4];"
                 : "=r"(a[0]), "=r"(a[1]), "=r"(a[2]), "=r"(a[3]) : "r"(addr));
}
__device__ __forceinline__ void mma16816(float* c, const uint32_t* a, const uint32_t* b) {
    asm volatile("mma.sync.aligned.m16n8k16.row.col.f32.bf16.bf16.f32 "
                 "{%0,%1,%2,%3},{%4,%5,%6,%7},{%8,%9},{%0,%1,%2,%3};"
                 : "+f"(c[0]), "+f"(c[1]), "+f"(c[2]), "+f"(c[3])
                 : "r"(a[0]), "r"(a[1]), "r"(a[2]), "r"(a[3]), "r"(b[0]), "r"(b[1]));
}
__device__ __forceinline__ void cp_async16(uint32_t dst, const void* src) {
    asm volatile("cp.async.cg.shared.global [%0], [%1], 16;" :: "r"(dst), "l"(src));
}

// fp32 rows of 128 -> two bf16 planes in smem, rows of 256B, XOR-16B swizzle
__device__ __forceinline__ void w_row_sts(char* sm, uint32_t oh, uint32_t ol,
                                          const float* __restrict__ src,
                                          int nrows, int tid, int nthreads) {
    for (int idx = tid * 4; idx < nrows * 128; idx += nthreads * 4) {
        int m = idx >> 7, k = idx & 127;
        float4 w = *(const float4*)(src + m * 128 + k);
        uint32_t h0, l0, h1, l1;
        bf16_split2(w.x, w.y, h0, l0);
        bf16_split2(w.z, w.w, h1, l1);
        uint32_t byte = (uint32_t)(m * 256) + (((uint32_t)(k * 2)) ^ (((uint32_t)m & 7) << 4));
        *(uint2*)(sm + oh + byte) = make_uint2(h0, h1);
        *(uint2*)(sm + ol + byte) = make_uint2(l0, l1);
    }
}

// ---------------------------------------------------------------------------
__global__ void k_zero() {
    int i = blockIdx.x * blockDim.x + threadIdx.x;
    if (i < NB * 4096) g_S[i] = 0.0f;
    else g_Z[i - NB * 4096] = 0.0f;
}

// ---------------------------------------------------------------------------
// k_kvctx (structure as R8; GEMMs restructured to share hi/lo fragment loads)
#define O_XHI 131072u
#define O_XLO 147456u
#define O_EKH 163840u
#define O_EKL 180224u
#define O_VH  196608u
#define O_VL  212992u

__global__ void __launch_bounds__(256, 1)
k_kvctx(const float* __restrict__ x, const float* __restrict__ Wqkv) {
    extern __shared__ char sm[];
    const uint32_t smb = smem_u32(sm);
    const int tid = threadIdx.x, wid = tid >> 5, lane = tid & 31;
    const int mbase = wid * 32;
    const int h = wid >> 1, mh = wid & 1;

    w_row_sts(sm, 0u, 65536u, Wqkv + 128 * 128, 256, tid, 256);

    int per = (NTILES + GRID_SM - 1) / GRID_SM;   // 27
    int lo = blockIdx.x * per, hi = min(NTILES, lo + per);

    float CS[4][4];
    float zacc[4];
    int curb = -1;

    float4 px[8];
    if (lo < hi) {
        const float* xb = x + (size_t)(lo >> 8) * NCH * NW + (size_t)(lo & 255) * 64;
        #pragma unroll
        for (int it = 0; it < 8; it++) {
            int idx = tid * 4 + it * 1024;
            px[it] = *(const float4*)(xb + (size_t)(idx >> 6) * NW + (idx & 63));
        }
    }

    for (int tile = lo; tile < hi; tile++) {
        int b = tile >> 8;
        if (b != curb) {
            if (curb >= 0) {
                float* gS = g_S + curb * 4096 + h * 1024;
                int d0 = mh * 16 + (lane >> 2);
                #pragma unroll
                for (int nt = 0; nt < 4; nt++) {
                    int e = nt * 8 + 2 * (lane & 3);
                    atomicAdd(gS + d0 * 32 + e,           CS[nt][0]);
                    atomicAdd(gS + d0 * 32 + e + 1,       CS[nt][1]);
                    atomicAdd(gS + (d0 + 8) * 32 + e,     CS[nt][2]);
                    atomicAdd(gS + (d0 + 8) * 32 + e + 1, CS[nt][3]);
                }
                if (wid < 4 && (lane & 3) == 0) {
                    #pragma unroll
                    for (int mt = 0; mt < 2; mt++) {
                        atomicAdd(g_Z + curb * 128 + mbase + mt * 16 + (lane >> 2),     zacc[mt * 2]);
                        atomicAdd(g_Z + curb * 128 + mbase + mt * 16 + (lane >> 2) + 8, zacc[mt * 2 + 1]);
                    }
                }
            }
            #pragma unroll
            for (int nt = 0; nt < 4; nt++)
                #pragma unroll
                for (int q = 0; q < 4; q++) CS[nt][q] = 0.0f;
            zacc[0] = zacc[1] = zacc[2] = zacc[3] = 0.0f;
            curb = b;
        }

        #pragma unroll
        for (int it = 0; it < 8; it++) {
            int idx = tid * 4 + it * 1024;
            int k = idx >> 6, n = idx & 63;
            uint32_t h0, l0, h1, l1;
            bf16_split2(px[it].x, px[it].y, h0, l0);
            bf16_split2(px[it].z, px[it].w, h1, l1);
            uint32_t byte = (uint32_t)(k * 128) + (((uint32_t)(n * 2)) ^ (((uint32_t)k & 7) << 4));
            *(uint2*)(sm + O_XHI + byte) = make_uint2(h0, h1);
            *(uint2*)(sm + O_XLO + byte) = make_uint2(l0, l1);
        }
        if (tile + 1 < hi) {
            int nt2 = tile + 1;
            const float* xb = x + (size_t)(nt2 >> 8) * NCH * NW + (size_t)(nt2 & 255) * 64;
            #pragma unroll
            for (int it = 0; it < 8; it++) {
                int idx = tid * 4 + it * 1024;
                px[it] = *(const float4*)(xb + (size_t)(idx >> 6) * NW + (idx & 63));
            }
        }
        __syncthreads();

        // main GEMM: kv(256x64) = W_kv @ x, bf16x3 with shared hi/lo loads
        float C[2][8][4];
        #pragma unroll
        for (int i = 0; i < 2; i++)
            #pragma unroll
            for (int j = 0; j < 8; j++)
                #pragma unroll
                for (int q = 0; q < 4; q++) C[i][j][q] = 0.0f;

        #pragma unroll
        for (int ks = 0; ks < 8; ks++) {
            int k0 = ks * 16;
            uint32_t ah[2][4], al[2][4], bh[4][4], bl[4][4];
            #pragma unroll
            for (int mt = 0; mt < 2; mt++) {
                int row = mbase + mt * 16 + (lane & 15);
                uint32_t kb = (uint32_t)((k0 + ((lane >> 4) << 3)) * 2);
                uint32_t off = (uint32_t)(row * 256) + (kb ^ (((uint32_t)row & 7) << 4));
                ldsm_x4(ah[mt], smb + off);
                ldsm_x4(al[mt], smb + 65536u + off);
            }
            #pragma unroll
            for (int t2 = 0; t2 < 4; t2++) {
                int krow = k0 + (lane & 15);
                uint32_t nb = (uint32_t)((t2 * 16 + ((lane >> 4) << 3)) * 2);
                uint32_t off = (uint32_t)(krow * 128) + (nb ^ (((uint32_t)krow & 7) << 4));
                ldsm_x4t(bh[t2], smb + O_XHI + off);
                ldsm_x4t(bl[t2], smb + O_XLO + off);
            }
            #pragma unroll
            for (int mt = 0; mt < 2; mt++)
                #pragma unroll
                for (int t2 = 0; t2 < 4; t2++) {
                    mma16816(C[mt][t2 * 2],     ah[mt], &bh[t2][0]);
                    mma16816(C[mt][t2 * 2 + 1], ah[mt], &bh[t2][2]);
                    mma16816(C[mt][t2 * 2],     ah[mt], &bl[t2][0]);
                    mma16816(C[mt][t2 * 2 + 1], ah[mt], &bl[t2][2]);
                    mma16816(C[mt][t2 * 2],     al[mt], &bh[t2][0]);
                    mma16816(C[mt][t2 * 2 + 1], al[mt], &bh[t2][2]);
                }
        }

        if (wid < 4) {
            float zp[4] = {0.0f, 0.0f, 0.0f, 0.0f};
            #pragma unroll
            for (int mt = 0; mt < 2; mt++) {
                int r0 = mbase + mt * 16 + (lane >> 2);
                int r1 = r0 + 8;
                #pragma unroll
                for (int nt = 0; nt < 8; nt++) {
                    int cc = nt * 8 + 2 * (lane & 3);
                    float e0 = __expf(C[mt][nt][0]);
                    float e1 = __expf(C[mt][nt][1]);
                    float e2 = __expf(C[mt][nt][2]);
                    float e3 = __expf(C[mt][nt][3]);
                    zp[mt * 2]     += e0 + e1;
                    zp[mt * 2 + 1] += e2 + e3;
                    uint32_t hh, ll;
                    bf16_split2(e0, e1, hh, ll);
                    uint32_t byte = (uint32_t)(r0 * 128)
                                  + (((uint32_t)(cc * 2)) ^ (((uint32_t)r0 & 7) << 4));
                    *(uint32_t*)(sm + O_EKH + byte) = hh;
                    *(uint32_t*)(sm + O_EKL + byte) = ll;
                    bf16_split2(e2, e3, hh, ll);
                    byte = (uint32_t)(r1 * 128)
                         + (((uint32_t)(cc * 2)) ^ (((uint32_t)r1 & 7) << 4));
                    *(uint32_t*)(sm + O_EKH + byte) = hh;
                    *(uint32_t*)(sm + O_EKL + byte) = ll;
                }
            }
            #pragma unroll
            for (int i = 0; i < 4; i++) {
                zp[i] += __shfl_xor_sync(0xFFFFFFFFu, zp[i], 1);
                zp[i] += __shfl_xor_sync(0xFFFFFFFFu, zp[i], 2);
                zacc[i] += zp[i];
            }
        } else {
            #pragma unroll
            for (int mt = 0; mt < 2; mt++) {
                int r0 = mbase - 128 + mt * 16 + (lane >> 2);
                int r1 = r0 + 8;
                #pragma unroll
                for (int nt = 0; nt < 8; nt++) {
                    int cc = nt * 8 + 2 * (lane & 3);
                    uint32_t hh, ll;
                    bf16_split2(C[mt][nt][0], C[mt][nt][1], hh, ll);
                    uint32_t byte = (uint32_t)(r0 * 128)
                                  + (((uint32_t)(cc * 2)) ^ (((uint32_t)r0 & 7) << 4));
                    *(uint32_t*)(sm + O_VH + byte) = hh;
                    *(uint32_t*)(sm + O_VL + byte) = ll;
                    bf16_split2(C[mt][nt][2], C[mt][nt][3], hh, ll);
                    byte = (uint32_t)(r1 * 128)
                         + (((uint32_t)(cc * 2)) ^ (((uint32_t)r1 & 7) << 4));
                    *(uint32_t*)(sm + O_VH + byte) = hh;
                    *(uint32_t*)(sm + O_VL + byte) = ll;
                }
            }
        }
        __syncthreads();

        // S-GEMM with shared hi/lo loads
        {
            int arow = h * 32 + mh * 16 + (lane & 15);
            uint32_t acol = (uint32_t)((lane >> 4) << 4);
            int erow_in = ((lane >> 4) << 3) + (lane & 7);
            uint32_t bsel = (uint32_t)(((lane >> 3) & 1) << 4);
            #pragma unroll
            for (int ks = 0; ks < 4; ks++) {
                uint32_t kb = (uint32_t)(ks * 32);
                uint32_t aoff = (uint32_t)(arow * 128)
                              + ((kb + acol) ^ (((uint32_t)arow & 7) << 4));
                uint32_t Ah[4], Al[4];
                ldsm_x4(Ah, smb + O_EKH + aoff);
                ldsm_x4(Al, smb + O_EKL + aoff);
                #pragma unroll
                for (int et = 0; et < 2; et++) {
                    int er = h * 32 + et * 16 + erow_in;
                    uint32_t boff = (uint32_t)(er * 128)
                                  + ((kb + bsel) ^ (((uint32_t)er & 7) << 4));
                    uint32_t Bh[4], Bl[4];
                    ldsm_x4(Bh, smb + O_VH + boff);
                    ldsm_x4(Bl, smb + O_VL + boff);
                    mma16816(CS[et * 2],     Ah, &Bh[0]);
                    mma16816(CS[et * 2 + 1], Ah, &Bh[2]);
                    mma16816(CS[et * 2],     Ah, &Bl[0]);
                    mma16816(CS[et * 2 + 1], Ah, &Bl[2]);
                    mma16816(CS[et * 2],     Al, &Bh[0]);
                    mma16816(CS[et * 2 + 1], Al, &Bh[2]);
                }
            }
        }
    }

    if (curb >= 0) {
        float* gS = g_S + curb * 4096 + h * 1024;
        int d0 = mh * 16 + (lane >> 2);
        #pragma unroll
        for (int nt = 0; nt < 4; nt++) {
            int e = nt * 8 + 2 * (lane & 3);
            atomicAdd(gS + d0 * 32 + e,           CS[nt][0]);
            atomicAdd(gS + d0 * 32 + e + 1,       CS[nt][1]);
            atomicAdd(gS + (d0 + 8) * 32 + e,     CS[nt][2]);
            atomicAdd(gS + (d0 + 8) * 32 + e + 1, CS[nt][3]);
        }
        if (wid < 4 && (lane & 3) == 0) {
            #pragma unroll
            for (int mt = 0; mt < 2; mt++) {
                atomicAdd(g_Z + curb * 128 + mbase + mt * 16 + (lane >> 2),     zacc[mt * 2]);
                atomicAdd(g_Z + curb * 128 + mbase + mt * 16 + (lane >> 2) + 8, zacc[mt * 2 + 1]);
            }
        }
    }
}

// ---------------------------------------------------------------------------
__global__ void k_mbuild(const float* __restrict__ Wout) {
    __shared__ float sCtx[4096];
    __shared__ float sWo[16 * 128];
    int b = blockIdx.y, o0 = blockIdx.x * 16;
    int tid = threadIdx.x;
    for (int idx = tid * 4; idx < 4096; idx += 1024) {
        float4 sv = *(const float4*)(g_S + b * 4096 + idx);
        float z = g_Z[b * 128 + (idx >> 5)];
        float r = 1.0f / (z * (float)NW);
        sv.x *= r; sv.y *= r; sv.z *= r; sv.w *= r;
        *(float4*)(sCtx + idx) = sv;
    }
    for (int idx = tid * 4; idx < 2048; idx += 1024)
        *(float4*)(sWo + idx) = *(const float4*)(Wout + (size_t)o0 * 128 + idx);
    __syncthreads();
    for (int idx = tid; idx < 2048; idx += 256) {
        int orr = idx >> 7, hd = idx & 127;
        int hh = hd >> 5, d = hd & 31;
        const float* wrow = sWo + orr * 128 + hh * 32;
        const float* crow = sCtx + hh * 1024 + d * 32;
        float sum = 0.0f;
        #pragma unroll
        for (int e4 = 0; e4 < 8; e4++) {
            float4 w4 = *(const float4*)(wrow + e4 * 4);
            float4 c4 = *(const float4*)(crow + e4 * 4);
            sum += w4.x * c4.x + w4.y * c4.y + w4.z * c4.z + w4.w * c4.w;
        }
        g_M[b * 16384 + (o0 + orr) * 128 + hd] = SCALE_F * sum;
    }
}

// ---------------------------------------------------------------------------
// k_qout, 512 threads (as R9) with shared hi/lo fragment loads in DO_GEMM
#define Q_STG 163840u

__global__ void __launch_bounds__(512, 1)
k_qout(const float* __restrict__ x, const float* __restrict__ Wqkv,
       const float* __restrict__ b_out, const float* __restrict__ gamma,
       const float* __restrict__ beta, float* __restrict__ out) {
    extern __shared__ char sm[];
    __shared__ float sBias[128], sGamma[128], sBeta[128], sStat[128];
    __shared__ float sPS[256], sPQ[256];
    const uint32_t smb = smem_u32(sm);
    const int tid = threadIdx.x, wid = tid >> 5, lane = tid & 31;
    const int mbase = (wid >> 2) * 32;
    const int nbase = (wid & 3) * 16;
    const int wrow = wid >> 2;

    w_row_sts(sm, 0u, 32768u, Wqkv, 128, tid, 512);
    if (tid < 128) {
        sBias[tid] = b_out[tid]; sGamma[tid] = gamma[tid]; sBeta[tid] = beta[tid];
    }

    int per = (NTILES + GRID_SM - 1) / GRID_SM;
    int lo = blockIdx.x * per, hi = min(NTILES, lo + per);
    int curb = -1;

    for (int tile = lo; tile < hi; tile++) {
        int b = tile >> 8, n0 = (tile & 255) * 64;
        if (b != curb) {
            __syncthreads();
            w_row_sts(sm, 65536u, 98304u, g_M + (size_t)b * 16384, 128, tid, 512);
            curb = b;
        }
        __syncthreads();

        if (tile == lo) {
            const float* xb = x + (size_t)b * NCH * NW + n0;
            #pragma unroll
            for (int it = 0; it < 4; it++) {
                int idx = tid * 4 + it * 2048;
                int k = idx >> 6, n = idx & 63;
                float4 v = *(const float4*)(xb + (size_t)k * NW + n);
                uint32_t h0, l0, h1, l1;
                bf16_split2(v.x, v.y, h0, l0);
                bf16_split2(v.z, v.w, h1, l1);
                uint32_t byte = (uint32_t)(k * 128) + (((uint32_t)(n * 2)) ^ (((uint32_t)k & 7) << 4));
                *(uint2*)(sm + 131072u + byte) = make_uint2(h0, h1);
                *(uint2*)(sm + 147456u + byte) = make_uint2(l0, l1);
            }
        } else {
            asm volatile("cp.async.wait_group 0;" ::: "memory");
            #pragma unroll
            for (int it = 0; it < 4; it++) {
                int idx = tid * 4 + it * 2048;
                int k = idx >> 6, n = idx & 63;
                float4 v = *(const float4*)(sm + Q_STG + (uint32_t)idx * 4u);
                uint32_t h0, l0, h1, l1;
                bf16_split2(v.x, v.y, h0, l0);
                bf16_split2(v.z, v.w, h1, l1);
                uint32_t byte = (uint32_t)(k * 128) + (((uint32_t)(n * 2)) ^ (((uint32_t)k & 7) << 4));
                *(uint2*)(sm + 131072u + byte) = make_uint2(h0, h1);
                *(uint2*)(sm + 147456u + byte) = make_uint2(l0, l1);
            }
        }
        __syncthreads();

        if (tile + 1 < hi) {
            int nt2 = tile + 1;
            const float* xb = x + (size_t)(nt2 >> 8) * NCH * NW + (size_t)(nt2 & 255) * 64;
            #pragma unroll
            for (int it = 0; it < 4; it++) {
                int idx = tid * 4 + it * 2048;
                cp_async16(smb + Q_STG + (uint32_t)idx * 4u,
                           xb + (size_t)(idx >> 6) * NW + (idx & 63));
            }
            asm volatile("cp.async.commit_group;" ::: "memory");
        }

        float C[2][2][4];
        #define DO_GEMM(ABASE0)                                                          \
        do {                                                                             \
            _Pragma("unroll")                                                            \
            for (int i = 0; i < 2; i++)                                                  \
                _Pragma("unroll")                                                        \
                for (int j = 0; j < 2; j++)                                              \
                    _Pragma("unroll")                                                    \
                    for (int q = 0; q < 4; q++) C[i][j][q] = 0.0f;                       \
            _Pragma("unroll")                                                            \
            for (int ks = 0; ks < 8; ks++) {                                             \
                int k0 = ks * 16;                                                        \
                uint32_t ah[2][4], al[2][4], bh[4], bl[4];                               \
                _Pragma("unroll")                                                        \
                for (int mt = 0; mt < 2; mt++) {                                         \
                    int row = mbase + mt * 16 + (lane & 15);                             \
                    uint32_t kb = (uint32_t)((k0 + ((lane >> 4) << 3)) * 2);             \
                    uint32_t off = (uint32_t)(row * 256)                                 \
                                 + (kb ^ (((uint32_t)row & 7) << 4));                    \
                    ldsm_x4(ah[mt], smb + (ABASE0) + off);                               \
                    ldsm_x4(al[mt], smb + (ABASE0) + 32768u + off);                      \
                }                                                                        \
                {                                                                        \
                    int krow = k0 + (lane & 15);                                         \
                    uint32_t nb = (uint32_t)((nbase + ((lane >> 4) << 3)) * 2);          \
                    uint32_t off = (uint32_t)(krow * 128)                                \
                                 + (nb ^ (((uint32_t)krow & 7) << 4));                   \
                    ldsm_x4t(bh, smb + 131072u + off);                                   \
                    ldsm_x4t(bl, smb + 147456u + off);                                   \
                }                                                                        \
                _Pragma("unroll")                                                        \
                for (int mt = 0; mt < 2; mt++) {                                         \
                    mma16816(C[mt][0], ah[mt], &bh[0]);                                  \
                    mma16816(C[mt][1], ah[mt], &bh[2]);                                  \
                    mma16816(C[mt][0], ah[mt], &bl[0]);                                  \
                    mma16816(C[mt][1], ah[mt], &bl[2]);                                  \
                    mma16816(C[mt][0], al[mt], &bh[0]);                                  \
                    mma16816(C[mt][1], al[mt], &bh[2]);                                  \
                }                                                                        \
            }                                                                            \
        } while (0)

        DO_GEMM(0u);
        __syncthreads();

        {   // softmax over head-dim (warp rows = one head, 32 rows)
            #pragma unroll
            for (int nt = 0; nt < 2; nt++) {
                float p0 = 0.0f, p1 = 0.0f;
                #pragma unroll
                for (int mt = 0; mt < 2; mt++) {
                    #pragma unroll
                    for (int q = 0; q < 4; q++) C[mt][nt][q] = __expf(C[mt][nt][q]);
                    p0 += C[mt][nt][0] + C[mt][nt][2];
                    p1 += C[mt][nt][1] + C[mt][nt][3];
                }
                p0 += __shfl_xor_sync(0xFFFFFFFFu, p0, 4);
                p0 += __shfl_xor_sync(0xFFFFFFFFu, p0, 8);
                p0 += __shfl_xor_sync(0xFFFFFFFFu, p0, 16);
                p1 += __shfl_xor_sync(0xFFFFFFFFu, p1, 4);
                p1 += __shfl_xor_sync(0xFFFFFFFFu, p1, 8);
                p1 += __shfl_xor_sync(0xFFFFFFFFu, p1, 16);
                float r0 = __fdividef(1.0f, p0), r1 = __fdividef(1.0f, p1);
                #pragma unroll
                for (int mt = 0; mt < 2; mt++) {
                    C[mt][nt][0] *= r0; C[mt][nt][2] *= r0;
                    C[mt][nt][1] *= r1; C[mt][nt][3] *= r1;
                }
            }
            #pragma unroll
            for (int mt = 0; mt < 2; mt++)
                #pragma unroll
                for (int nt = 0; nt < 2; nt++) {
                    int r0 = mbase + mt * 16 + (lane >> 2);
                    int cc = nbase + nt * 8 + 2 * (lane & 3);
                    uint32_t hh, ll;
                    bf16_split2(C[mt][nt][0], C[mt][nt][1], hh, ll);
                    uint32_t byte = (uint32_t)(r0 * 128)
                                  + (((uint32_t)(cc * 2)) ^ (((uint32_t)r0 & 7) << 4));
                    *(uint32_t*)(sm + 131072 + byte) = hh;
                    *(uint32_t*)(sm + 147456 + byte) = ll;
                    int r1 = r0 + 8;
                    bf16_split2(C[mt][nt][2], C[mt][nt][3], hh, ll);
                    byte = (uint32_t)(r1 * 128)
                         + (((uint32_t)(cc * 2)) ^ (((uint32_t)r1 & 7) << 4));
                    *(uint32_t*)(sm + 131072 + byte) = hh;
                    *(uint32_t*)(sm + 147456 + byte) = ll;
                }
        }
        __syncthreads();

        DO_GEMM(65536u);
        #undef DO_GEMM

        {   // bias + LN partials from fragments
            float ps[2][2], pq[2][2];
            #pragma unroll
            for (int nt = 0; nt < 2; nt++) { ps[nt][0] = ps[nt][1] = pq[nt][0] = pq[nt][1] = 0.0f; }
            #pragma unroll
            for (int mt = 0; mt < 2; mt++) {
                int r0 = mbase + mt * 16 + (lane >> 2);
                float b0 = sBias[r0], b1 = sBias[r0 + 8];
                #pragma unroll
                for (int nt = 0; nt < 2; nt++) {
                    C[mt][nt][0] += b0; C[mt][nt][1] += b0;
                    C[mt][nt][2] += b1; C[mt][nt][3] += b1;
                    ps[nt][0] += C[mt][nt][0] + C[mt][nt][2];
                    ps[nt][1] += C[mt][nt][1] + C[mt][nt][3];
                    pq[nt][0] += C[mt][nt][0] * C[mt][nt][0] + C[mt][nt][2] * C[mt][nt][2];
                    pq[nt][1] += C[mt][nt][1] * C[mt][nt][1] + C[mt][nt][3] * C[mt][nt][3];
                }
            }
            #pragma unroll
            for (int nt = 0; nt < 2; nt++)
                #pragma unroll
                for (int cp = 0; cp < 2; cp++) {
                    ps[nt][cp] += __shfl_xor_sync(0xFFFFFFFFu, ps[nt][cp], 4);
                    ps[nt][cp] += __shfl_xor_sync(0xFFFFFFFFu, ps[nt][cp], 8);
                    ps[nt][cp] += __shfl_xor_sync(0xFFFFFFFFu, ps[nt][cp], 16);
                    pq[nt][cp] += __shfl_xor_sync(0xFFFFFFFFu, pq[nt][cp], 4);
                    pq[nt][cp] += __shfl_xor_sync(0xFFFFFFFFu, pq[nt][cp], 8);
                    pq[nt][cp] += __shfl_xor_sync(0xFFFFFFFFu, pq[nt][cp], 16);
                }
            if (lane < 4) {
                #pragma unroll
                for (int nt = 0; nt < 2; nt++) {
                    int cc = nbase + nt * 8 + 2 * lane;
                    sPS[wrow * 64 + cc]     = ps[nt][0];
                    sPS[wrow * 64 + cc + 1] = ps[nt][1];
                    sPQ[wrow * 64 + cc]     = pq[nt][0];
                    sPQ[wrow * 64 + cc + 1] = pq[nt][1];
                }
            }
        }
        __syncthreads();
        if (tid < 64) {
            float s  = sPS[tid] + sPS[64 + tid] + sPS[128 + tid] + sPS[192 + tid];
            float sq = sPQ[tid] + sPQ[64 + tid] + sPQ[128 + tid] + sPQ[192 + tid];
            float mean = s * (1.0f / 128.0f);
            float var = sq * (1.0f / 128.0f) - mean * mean;
            sStat[tid * 2] = mean;
            sStat[tid * 2 + 1] = rsqrtf(var + LN_EPS);
        }
        __syncthreads();

        {   // apply LN from fragments, store to global
            float* ob = out + (size_t)b * NCH * NW + n0;
            #pragma unroll
            for (int mt = 0; mt < 2; mt++) {
                int r0 = mbase + mt * 16 + (lane >> 2);
                int r1 = r0 + 8;
                float g0 = sGamma[r0], be0 = sBeta[r0];
                float g1 = sGamma[r1], be1 = sBeta[r1];
                #pragma unroll
                for (int nt = 0; nt < 2; nt++) {
                    int cc = nbase + nt * 8 + 2 * (lane & 3);
                    float m0 = sStat[2 * cc],       rs0 = sStat[2 * cc + 1];
                    float m1 = sStat[2 * (cc + 1)], rs1 = sStat[2 * (cc + 1) + 1];
                    *(float2*)(ob + (size_t)r0 * NW + cc) = make_float2(
                        (C[mt][nt][0] - m0) * rs0 * g0 + be0,
                        (C[mt][nt][1] - m1) * rs1 * g0 + be0);
                    *(float2*)(ob + (size_t)r1 * NW + cc) = make_float2(
                        (C[mt][nt][2] - m0) * rs0 * g1 + be1,
                        (C[mt][nt][3] - m1) * rs1 * g1 + be1);
                }
            }
        }
    }
}

// ---------------------------------------------------------------------------
extern "C" void kernel_launch(void* const* d_in, const int* in_sizes, int n_in,
                              void* d_out, int out_size) {
    const float* x    = (const float*)d_in[0];
    const float* Wqkv = (const float*)d_in[1];
    const float* Wout = (const float*)d_in[2];
    const float* bo   = (const float*)d_in[3];
    const float* gm   = (const float*)d_in[4];
    const float* bt   = (const float*)d_in[5];
    float* out = (float*)d_out;

    const int SMEM_A = 229376;
    const int SMEM_C = 196608;
    cudaFuncSetAttribute(k_kvctx, cudaFuncAttributeMaxDynamicSharedMemorySize, SMEM_A);
    cudaFuncSetAttribute(k_qout,  cudaFuncAttributeMaxDynamicSharedMemorySize, SMEM_C);

    k_zero<<<66, 1024>>>();
    k_kvctx<<<GRID_SM, 256, SMEM_A>>>(x, Wqkv);
    k_mbuild<<<dim3(8, 16), 256>>>(Wout);
    k_qout<<<GRID_SM, 512, SMEM_C>>>(x, Wqkv, bo, gm, bt, out);
}